// round 6
// baseline (speedup 1.0000x reference)
#include <cuda_runtime.h>
#include <cstdint>

// Problem constants
#define DM   1024
#define NH   16
#define HD   64
#define BB   2
#define TT   2048

// Scratch (device globals: allocation-free rule)
__device__ float g_qkv[3 * BB * NH * TT * HD];   // [which][b][h][t][d]
__device__ float g_att[BB * TT * DM];            // [b][t][h][d] == [B*T, C]

// ---------------------------------------------------------------------------
// tf32 helpers (portable PTX: works on plain sm_103 target)
// ---------------------------------------------------------------------------
__device__ __forceinline__ float to_tf32(float x) {
    uint32_t u;
    asm("cvt.rna.tf32.f32 %0, %1;" : "=r"(u) : "f"(x));
    return __uint_as_float(u);
}
__device__ __forceinline__ uint32_t tf32u(float x) {
    uint32_t u;
    asm("cvt.rna.tf32.f32 %0, %1;" : "=r"(u) : "f"(x));
    return u;
}

__device__ __forceinline__ void mma_tf32(float& c0, float& c1, float& c2, float& c3,
                                         uint32_t a0, uint32_t a1, uint32_t a2, uint32_t a3,
                                         uint32_t b0, uint32_t b1) {
    asm volatile(
        "mma.sync.aligned.m16n8k8.row.col.f32.tf32.tf32.f32 "
        "{%0,%1,%2,%3}, {%4,%5,%6,%7}, {%8,%9}, {%0,%1,%2,%3};"
        : "+f"(c0), "+f"(c1), "+f"(c2), "+f"(c3)
        : "r"(a0), "r"(a1), "r"(a2), "r"(a3), "r"(b0), "r"(b1));
}

__device__ __forceinline__ uint32_t smem_u32(const void* p) {
    uint32_t a;
    asm("{ .reg .u64 t; cvta.to.shared.u64 t, %1; cvt.u32.u64 %0, t; }"
        : "=r"(a) : "l"(p));
    return a;
}
__device__ __forceinline__ void cpa16(uint32_t saddr, const void* g) {
    asm volatile("cp.async.cg.shared.global [%0], [%1], 16;"
                 :: "r"(saddr), "l"(g) : "memory");
}
#define CP_COMMIT() asm volatile("cp.async.commit_group;" ::: "memory")
#define CP_WAIT2()  asm volatile("cp.async.wait_group 2;" ::: "memory")
#define CP_WAIT0()  asm volatile("cp.async.wait_group 0;" ::: "memory")

// ---------------------------------------------------------------------------
// tf32 tensor-core GEMM with 4-stage cp.async pipeline (unchanged from R5).
// ---------------------------------------------------------------------------
#define AS_STRIDE (128 * 20)
#define BS_STRIDE (16 * 136)
#define GSMEM_BYTES ((4 * AS_STRIDE + 4 * BS_STRIDE) * 4)

template <int MODE>
__global__ __launch_bounds__(256) void mma_gemm(const float* __restrict__ A,
                                                const float* __restrict__ Bw,
                                                const float* __restrict__ bias,
                                                float* __restrict__ C,
                                                int M, int N, int K)
{
    extern __shared__ float dsm[];
    float* AsF = dsm;
    float* BsF = dsm + 4 * AS_STRIDE;
    const uint32_t abase = smem_u32(AsF);
    const uint32_t bbase = smem_u32(BsF);

    const int tid  = threadIdx.x;
    const int bm   = blockIdx.y * 128;
    const int bn   = blockIdx.x * 128;
    const int w    = tid >> 5;
    const int lane = tid & 31;
    const int g    = lane >> 2;
    const int t    = lane & 3;
    const int m0   = (w & 3) * 32;
    const int n0   = (w >> 2) * 64;

    const float* Aeff = (MODE == 0) ? A : (const float*)g_att;

    float acc[2][8][4];
#pragma unroll
    for (int mt = 0; mt < 2; mt++)
#pragma unroll
        for (int nt = 0; nt < 8; nt++)
#pragma unroll
            for (int r = 0; r < 4; r++) acc[mt][nt][r] = 0.f;

    const int av0 = tid,        av1 = tid + 256;
    const int ar0 = av0 >> 2,   ac0 = (av0 & 3) * 4;
    const int ar1 = av1 >> 2,   ac1 = (av1 & 3) * 4;
    const int br0 = av0 >> 5,   bc0 = (av0 & 31) * 4;
    const int br1 = av1 >> 5,   bc1 = (av1 & 31) * 4;

    const int NC = K >> 4;

    auto issue = [&](int c) {
        const int s = c & 3;
        const uint32_t as = abase + (uint32_t)(s * AS_STRIDE) * 4u;
        const uint32_t bs = bbase + (uint32_t)(s * BS_STRIDE) * 4u;
        const int k0 = c << 4;
        cpa16(as + (uint32_t)(ar0 * 20 + ac0) * 4u,
              Aeff + (size_t)(bm + ar0) * K + k0 + ac0);
        cpa16(as + (uint32_t)(ar1 * 20 + ac1) * 4u,
              Aeff + (size_t)(bm + ar1) * K + k0 + ac1);
        cpa16(bs + (uint32_t)(br0 * 136 + bc0) * 4u,
              Bw + (size_t)(k0 + br0) * N + bn + bc0);
        cpa16(bs + (uint32_t)(br1 * 136 + bc1) * 4u,
              Bw + (size_t)(k0 + br1) * N + bn + bc1);
    };

    issue(0); CP_COMMIT();
    issue(1); CP_COMMIT();
    issue(2); CP_COMMIT();

    for (int c = 0; c < NC; c++) {
        const int st = c & 3;
        CP_WAIT2();
        __syncthreads();

        if (c + 3 < NC) issue(c + 3);
        CP_COMMIT();

        const float* As = AsF + st * AS_STRIDE;
        const float* Bs = BsF + st * BS_STRIDE;
#pragma unroll
        for (int ks = 0; ks < 2; ks++) {
            const int kb = ks * 8;
            uint32_t af[2][4], bf[8][2];
#pragma unroll
            for (int mt = 0; mt < 2; mt++) {
                const int m = m0 + mt * 16 + g;
                af[mt][0] = tf32u(As[m * 20 + kb + t]);
                af[mt][1] = tf32u(As[(m + 8) * 20 + kb + t]);
                af[mt][2] = tf32u(As[m * 20 + kb + t + 4]);
                af[mt][3] = tf32u(As[(m + 8) * 20 + kb + t + 4]);
            }
#pragma unroll
            for (int nt = 0; nt < 8; nt++) {
                const int n = n0 + nt * 8 + g;
                bf[nt][0] = tf32u(Bs[(kb + t) * 136 + n]);
                bf[nt][1] = tf32u(Bs[(kb + t + 4) * 136 + n]);
            }
#pragma unroll
            for (int mt = 0; mt < 2; mt++)
#pragma unroll
                for (int nt = 0; nt < 8; nt++)
                    mma_tf32(acc[mt][nt][0], acc[mt][nt][1],
                             acc[mt][nt][2], acc[mt][nt][3],
                             af[mt][0], af[mt][1], af[mt][2], af[mt][3],
                             bf[nt][0], bf[nt][1]);
        }
    }

    const int ng = bn + n0;
    if (MODE == 0) {
        const int which = ng >> 10;
        const int rem   = ng & 1023;
        const int h     = rem >> 6;
#pragma unroll
        for (int mt = 0; mt < 2; mt++) {
            const int row0 = bm + m0 + mt * 16 + g;
            const int row1 = row0 + 8;
            const int b0i = row0 >> 11, t0i = row0 & 2047;
            const int b1i = row1 >> 11, t1i = row1 & 2047;
            float* base0 = g_qkv + ((size_t)((which * BB + b0i) * NH + h) * TT + t0i) * HD;
            float* base1 = g_qkv + ((size_t)((which * BB + b1i) * NH + h) * TT + t1i) * HD;
#pragma unroll
            for (int nt = 0; nt < 8; nt++) {
                const int d = nt * 8 + 2 * t;
                const float bx = bias[ng + d], by = bias[ng + d + 1];
                float2 o0 = { acc[mt][nt][0] + bx, acc[mt][nt][1] + by };
                float2 o1 = { acc[mt][nt][2] + bx, acc[mt][nt][3] + by };
                *(float2*)(base0 + d) = o0;
                *(float2*)(base1 + d) = o1;
            }
        }
    } else {
#pragma unroll
        for (int mt = 0; mt < 2; mt++) {
            const int row0 = bm + m0 + mt * 16 + g;
            const int row1 = row0 + 8;
#pragma unroll
            for (int nt = 0; nt < 8; nt++) {
                const int n = ng + nt * 8 + 2 * t;
                const float bx = bias[n], by = bias[n + 1];
                float2 o0 = { acc[mt][nt][0] + bx, acc[mt][nt][1] + by };
                float2 o1 = { acc[mt][nt][2] + bx, acc[mt][nt][3] + by };
                *(float2*)(C + (size_t)row0 * N + n) = o0;
                *(float2*)(C + (size_t)row1 * N + n) = o1;
            }
        }
    }
}

// ---------------------------------------------------------------------------
// Flash attention, tf32 mma.sync + 2-stage cp.async K/V double buffer.
// Raw fp32 lands in smem; an in-place fixup pass applies cvt.rna.tf32 once
// per element. Next tile's copy is issued under the current tile's compute.
// ---------------------------------------------------------------------------
#define FL_TILE  (64 * 68)                       // floats per K (or V) stage
#define FLASH_SMEM ((4 * FL_TILE + 128 * 68) * 4)  // 2 stages K+V, plus Ps

__global__ __launch_bounds__(256, 2) void flash_mma()
{
    extern __shared__ float sm[];
    // stage s: K at sm + s*2*FL_TILE, V at +FL_TILE
    float* Ps = sm + 4 * FL_TILE;    // [128][68]: Q staging, then P (tf32)
    const uint32_t smb = smem_u32(sm);

    const int tid  = threadIdx.x;
    const int w    = tid >> 5;
    const int lane = tid & 31;
    const int g    = lane >> 2;
    const int t    = lane & 3;
    const int qt   = (int)gridDim.x - 1 - (int)blockIdx.x;  // heavy CTAs first
    const int h    = blockIdx.y;
    const int b    = blockIdx.z;
    const int q_base = qt * 128;
    const int mb     = w * 16;

    const float* Qg = g_qkv + ((size_t)((0 * BB + b) * NH + h) * TT) * HD;
    const float* Kg = g_qkv + ((size_t)((1 * BB + b) * NH + h) * TT) * HD;
    const float* Vg = g_qkv + ((size_t)((2 * BB + b) * NH + h) * TT) * HD;

    // copy/fixup indexing: 4 float4 per thread per 64x64 tile
    int frow[4], fc4[4];
#pragma unroll
    for (int j = 0; j < 4; j++) {
        const int v = tid + 256 * j;
        frow[j] = v >> 4;
        fc4[j]  = (v & 15) * 4;
    }

    auto issue_kv = [&](int kt) {
        const int s = kt & 1;
        const uint32_t kb = smb + (uint32_t)(s * 2 * FL_TILE) * 4u;
        const uint32_t vb = kb + (uint32_t)FL_TILE * 4u;
        const float* Kt = Kg + (size_t)(kt * 64) * HD;
        const float* Vt = Vg + (size_t)(kt * 64) * HD;
#pragma unroll
        for (int j = 0; j < 4; j++) {
            const uint32_t so = (uint32_t)(frow[j] * 68 + fc4[j]) * 4u;
            const size_t   go = (size_t)frow[j] * HD + fc4[j];
            cpa16(kb + so, Kt + go);
            cpa16(vb + so, Vt + go);
        }
    };

    // stage Q tile (prescaled by 1/sqrt(64), tf32-rounded) into Ps
    for (int i = tid; i < 2048; i += 256) {
        const int row = i >> 4, c4 = (i & 15) * 4;
        float4 v = *(const float4*)(Qg + (size_t)(q_base + row) * HD + c4);
        v.x = to_tf32(v.x * 0.125f);
        v.y = to_tf32(v.y * 0.125f);
        v.z = to_tf32(v.z * 0.125f);
        v.w = to_tf32(v.w * 0.125f);
        *(float4*)&Ps[row * 68 + c4] = v;
    }
    issue_kv(0); CP_COMMIT();
    __syncthreads();

    // Q fragments live in registers for the whole kernel
    uint32_t qa[8][4];
#pragma unroll
    for (int ks = 0; ks < 8; ks++) {
        const int kb = ks * 8;
        qa[ks][0] = __float_as_uint(Ps[(mb + g) * 68 + kb + t]);
        qa[ks][1] = __float_as_uint(Ps[(mb + g + 8) * 68 + kb + t]);
        qa[ks][2] = __float_as_uint(Ps[(mb + g) * 68 + kb + t + 4]);
        qa[ks][3] = __float_as_uint(Ps[(mb + g + 8) * 68 + kb + t + 4]);
    }

    float oacc[8][4];
#pragma unroll
    for (int nt = 0; nt < 8; nt++)
#pragma unroll
        for (int r = 0; r < 4; r++) oacc[nt][r] = 0.f;
    float m0 = -1e30f, m1 = -1e30f, l0 = 0.f, l1 = 0.f;
    const int r0 = q_base + mb + g, r1 = r0 + 8;

    const int nkt = 2 * qt + 2;
    for (int kt = 0; kt < nkt; kt++) {
        const int st = kt & 1;
        float* Ks = sm + st * 2 * FL_TILE;
        float* Vs = Ks + FL_TILE;

        CP_WAIT0();
        __syncthreads();   // tile kt visible everywhere; all done with compute kt-1

        // issue next tile's copy (other stage; freed by the barrier above)
        if (kt + 1 < nkt) issue_kv(kt + 1);
        CP_COMMIT();

        // in-place tf32 fixup (once per element)
#pragma unroll
        for (int j = 0; j < 4; j++) {
            float* kp = &Ks[frow[j] * 68 + fc4[j]];
            float* vp = &Vs[frow[j] * 68 + fc4[j]];
            float4 kv = *(float4*)kp;
            kv.x = to_tf32(kv.x); kv.y = to_tf32(kv.y);
            kv.z = to_tf32(kv.z); kv.w = to_tf32(kv.w);
            *(float4*)kp = kv;
            float4 vv = *(float4*)vp;
            vv.x = to_tf32(vv.x); vv.y = to_tf32(vv.y);
            vv.z = to_tf32(vv.z); vv.w = to_tf32(vv.w);
            *(float4*)vp = vv;
        }
        __syncthreads();   // fixup complete

        // S = Q @ K^T   (16x64 per warp)
        float sacc[8][4];
#pragma unroll
        for (int nt = 0; nt < 8; nt++)
#pragma unroll
            for (int r = 0; r < 4; r++) sacc[nt][r] = 0.f;
#pragma unroll
        for (int ks = 0; ks < 8; ks++) {
            const int kb = ks * 8;
            uint32_t bf[8][2];
#pragma unroll
            for (int nt = 0; nt < 8; nt++) {
                bf[nt][0] = __float_as_uint(Ks[(nt * 8 + g) * 68 + kb + t]);
                bf[nt][1] = __float_as_uint(Ks[(nt * 8 + g) * 68 + kb + t + 4]);
            }
#pragma unroll
            for (int nt = 0; nt < 8; nt++)
                mma_tf32(sacc[nt][0], sacc[nt][1], sacc[nt][2], sacc[nt][3],
                         qa[ks][0], qa[ks][1], qa[ks][2], qa[ks][3],
                         bf[nt][0], bf[nt][1]);
        }

        // causal mask (only the two diagonal tiles of this CTA)
        if (kt >= 2 * qt) {
            const int sb = kt * 64;
#pragma unroll
            for (int nt = 0; nt < 8; nt++) {
                const int c0 = sb + nt * 8 + 2 * t, c1 = c0 + 1;
                if (c0 > r0) sacc[nt][0] = -1e30f;
                if (c1 > r0) sacc[nt][1] = -1e30f;
                if (c0 > r1) sacc[nt][2] = -1e30f;
                if (c1 > r1) sacc[nt][3] = -1e30f;
            }
        }

        // online softmax
        float mx0 = -1e30f, mx1 = -1e30f;
#pragma unroll
        for (int nt = 0; nt < 8; nt++) {
            mx0 = fmaxf(mx0, fmaxf(sacc[nt][0], sacc[nt][1]));
            mx1 = fmaxf(mx1, fmaxf(sacc[nt][2], sacc[nt][3]));
        }
        mx0 = fmaxf(mx0, __shfl_xor_sync(0xffffffffu, mx0, 1));
        mx0 = fmaxf(mx0, __shfl_xor_sync(0xffffffffu, mx0, 2));
        mx1 = fmaxf(mx1, __shfl_xor_sync(0xffffffffu, mx1, 1));
        mx1 = fmaxf(mx1, __shfl_xor_sync(0xffffffffu, mx1, 2));

        const float mn0 = fmaxf(m0, mx0), mn1 = fmaxf(m1, mx1);
        const float f0 = __expf(m0 - mn0), f1 = __expf(m1 - mn1);
        float ls0 = 0.f, ls1 = 0.f;
#pragma unroll
        for (int nt = 0; nt < 8; nt++) {
            const float p00 = __expf(sacc[nt][0] - mn0);
            const float p01 = __expf(sacc[nt][1] - mn0);
            const float p10 = __expf(sacc[nt][2] - mn1);
            const float p11 = __expf(sacc[nt][3] - mn1);
            ls0 += p00 + p01;
            ls1 += p10 + p11;
            float2 s0 = { to_tf32(p00), to_tf32(p01) };
            float2 s1 = { to_tf32(p10), to_tf32(p11) };
            *(float2*)&Ps[(mb + g) * 68 + nt * 8 + 2 * t]     = s0;
            *(float2*)&Ps[(mb + g + 8) * 68 + nt * 8 + 2 * t] = s1;
        }
        ls0 += __shfl_xor_sync(0xffffffffu, ls0, 1);
        ls0 += __shfl_xor_sync(0xffffffffu, ls0, 2);
        ls1 += __shfl_xor_sync(0xffffffffu, ls1, 1);
        ls1 += __shfl_xor_sync(0xffffffffu, ls1, 2);
        l0 = l0 * f0 + ls0;
        l1 = l1 * f1 + ls1;
        m0 = mn0; m1 = mn1;
#pragma unroll
        for (int nt = 0; nt < 8; nt++) {
            oacc[nt][0] *= f0; oacc[nt][1] *= f0;
            oacc[nt][2] *= f1; oacc[nt][3] *= f1;
        }
        __syncwarp();   // P rows are private to this warp

        // O += P @ V
#pragma unroll
        for (int ks = 0; ks < 8; ks++) {
            const int kb = ks * 8;
            uint32_t pa[4];
            pa[0] = __float_as_uint(Ps[(mb + g) * 68 + kb + t]);
            pa[1] = __float_as_uint(Ps[(mb + g + 8) * 68 + kb + t]);
            pa[2] = __float_as_uint(Ps[(mb + g) * 68 + kb + t + 4]);
            pa[3] = __float_as_uint(Ps[(mb + g + 8) * 68 + kb + t + 4]);
            uint32_t bf[8][2];
#pragma unroll
            for (int nt = 0; nt < 8; nt++) {
                bf[nt][0] = __float_as_uint(Vs[(kb + t) * 68 + nt * 8 + g]);
                bf[nt][1] = __float_as_uint(Vs[(kb + t + 4) * 68 + nt * 8 + g]);
            }
#pragma unroll
            for (int nt = 0; nt < 8; nt++)
                mma_tf32(oacc[nt][0], oacc[nt][1], oacc[nt][2], oacc[nt][3],
                         pa[0], pa[1], pa[2], pa[3], bf[nt][0], bf[nt][1]);
        }
    }

    // epilogue
    const float i0 = 1.0f / l0, i1 = 1.0f / l1;
    float* O0 = g_att + ((size_t)(b * TT + r0) * NH + h) * HD;
    float* O1 = g_att + ((size_t)(b * TT + r1) * NH + h) * HD;
#pragma unroll
    for (int nt = 0; nt < 8; nt++) {
        const int d = nt * 8 + 2 * t;
        float2 o0 = { oacc[nt][0] * i0, oacc[nt][1] * i0 };
        float2 o1 = { oacc[nt][2] * i1, oacc[nt][3] * i1 };
        *(float2*)(O0 + d) = o0;
        *(float2*)(O1 + d) = o1;
    }
}

// ---------------------------------------------------------------------------
// kernel_launch
// ---------------------------------------------------------------------------
extern "C" void kernel_launch(void* const* d_in, const int* in_sizes, int n_in,
                              void* d_out, int out_size)
{
    const float* x      = (const float*)d_in[0];
    const float* w_qkv  = (const float*)d_in[1];
    const float* b_qkv  = (const float*)d_in[2];
    const float* w_proj = (const float*)d_in[3];
    const float* b_proj = (const float*)d_in[4];
    float* out = (float*)d_out;

    const int M = BB * TT;  // 4096

    cudaFuncSetAttribute(mma_gemm<0>, cudaFuncAttributeMaxDynamicSharedMemorySize, GSMEM_BYTES);
    cudaFuncSetAttribute(mma_gemm<1>, cudaFuncAttributeMaxDynamicSharedMemorySize, GSMEM_BYTES);
    cudaFuncSetAttribute(flash_mma, cudaFuncAttributeMaxDynamicSharedMemorySize, FLASH_SMEM);

    // 1) QKV projection (tf32 mma.sync + cp.async pipeline) -> g_qkv
    mma_gemm<0><<<dim3(3 * DM / 128, M / 128), 256, GSMEM_BYTES>>>(x, w_qkv, b_qkv, nullptr, M, 3 * DM, DM);

    // 2) causal flash attention (tf32 mma.sync + cp.async) -> g_att
    flash_mma<<<dim3(TT / 128, NH, BB), 256, FLASH_SMEM>>>();

    // 3) output projection (tf32 mma.sync + cp.async pipeline) -> out
    mma_gemm<1><<<dim3(DM / 128, M / 128), 256, GSMEM_BYTES>>>(nullptr, w_proj, b_proj, out, M, DM, DM);
}

// round 7
// speedup vs baseline: 1.5797x; 1.5797x over previous
#include <cuda_runtime.h>
#include <cstdint>

// Problem constants
#define DM   1024
#define NH   16
#define HD   64
#define BB   2
#define TT   2048

// Scratch (device globals: allocation-free rule)
__device__ float g_qkv[3 * BB * NH * TT * HD];   // [which][b][h][t][d]
__device__ float g_att[BB * TT * DM];            // [b][t][h][d] == [B*T, C]

// ---------------------------------------------------------------------------
// tf32 helpers (portable PTX: works on plain sm_103 target)
// ---------------------------------------------------------------------------
__device__ __forceinline__ float to_tf32(float x) {
    uint32_t u;
    asm("cvt.rna.tf32.f32 %0, %1;" : "=r"(u) : "f"(x));
    return __uint_as_float(u);
}
__device__ __forceinline__ uint32_t tf32u(float x) {
    uint32_t u;
    asm("cvt.rna.tf32.f32 %0, %1;" : "=r"(u) : "f"(x));
    return u;
}

__device__ __forceinline__ void mma_tf32(float& c0, float& c1, float& c2, float& c3,
                                         uint32_t a0, uint32_t a1, uint32_t a2, uint32_t a3,
                                         uint32_t b0, uint32_t b1) {
    asm volatile(
        "mma.sync.aligned.m16n8k8.row.col.f32.tf32.tf32.f32 "
        "{%0,%1,%2,%3}, {%4,%5,%6,%7}, {%8,%9}, {%0,%1,%2,%3};"
        : "+f"(c0), "+f"(c1), "+f"(c2), "+f"(c3)
        : "r"(a0), "r"(a1), "r"(a2), "r"(a3), "r"(b0), "r"(b1));
}

__device__ __forceinline__ uint32_t smem_u32(const void* p) {
    uint32_t a;
    asm("{ .reg .u64 t; cvta.to.shared.u64 t, %1; cvt.u32.u64 %0, t; }"
        : "=r"(a) : "l"(p));
    return a;
}
__device__ __forceinline__ void cpa16(uint32_t saddr, const void* g) {
    asm volatile("cp.async.cg.shared.global [%0], [%1], 16;"
                 :: "r"(saddr), "l"(g) : "memory");
}
#define CP_COMMIT() asm volatile("cp.async.commit_group;" ::: "memory")
#define CP_WAIT2()  asm volatile("cp.async.wait_group 2;" ::: "memory")

// ---------------------------------------------------------------------------
// tf32 tensor-core GEMM with 4-stage cp.async pipeline (R5 known-good).
// C[M,N] = A[M,K] @ B[K,N] + bias[N].  BM=BN=128, BK=16, 8 warps (32x64 each).
// ---------------------------------------------------------------------------
#define AS_STRIDE (128 * 20)
#define BS_STRIDE (16 * 136)
#define GSMEM_BYTES ((4 * AS_STRIDE + 4 * BS_STRIDE) * 4)

template <int MODE>
__global__ __launch_bounds__(256) void mma_gemm(const float* __restrict__ A,
                                                const float* __restrict__ Bw,
                                                const float* __restrict__ bias,
                                                float* __restrict__ C,
                                                int M, int N, int K)
{
    extern __shared__ float dsm[];
    float* AsF = dsm;
    float* BsF = dsm + 4 * AS_STRIDE;
    const uint32_t abase = smem_u32(AsF);
    const uint32_t bbase = smem_u32(BsF);

    const int tid  = threadIdx.x;
    const int bm   = blockIdx.y * 128;
    const int bn   = blockIdx.x * 128;
    const int w    = tid >> 5;
    const int lane = tid & 31;
    const int g    = lane >> 2;
    const int t    = lane & 3;
    const int m0   = (w & 3) * 32;
    const int n0   = (w >> 2) * 64;

    const float* Aeff = (MODE == 0) ? A : (const float*)g_att;

    float acc[2][8][4];
#pragma unroll
    for (int mt = 0; mt < 2; mt++)
#pragma unroll
        for (int nt = 0; nt < 8; nt++)
#pragma unroll
            for (int r = 0; r < 4; r++) acc[mt][nt][r] = 0.f;

    const int av0 = tid,        av1 = tid + 256;
    const int ar0 = av0 >> 2,   ac0 = (av0 & 3) * 4;
    const int ar1 = av1 >> 2,   ac1 = (av1 & 3) * 4;
    const int br0 = av0 >> 5,   bc0 = (av0 & 31) * 4;
    const int br1 = av1 >> 5,   bc1 = (av1 & 31) * 4;

    const int NC = K >> 4;

    auto issue = [&](int c) {
        const int s = c & 3;
        const uint32_t as = abase + (uint32_t)(s * AS_STRIDE) * 4u;
        const uint32_t bs = bbase + (uint32_t)(s * BS_STRIDE) * 4u;
        const int k0 = c << 4;
        cpa16(as + (uint32_t)(ar0 * 20 + ac0) * 4u,
              Aeff + (size_t)(bm + ar0) * K + k0 + ac0);
        cpa16(as + (uint32_t)(ar1 * 20 + ac1) * 4u,
              Aeff + (size_t)(bm + ar1) * K + k0 + ac1);
        cpa16(bs + (uint32_t)(br0 * 136 + bc0) * 4u,
              Bw + (size_t)(k0 + br0) * N + bn + bc0);
        cpa16(bs + (uint32_t)(br1 * 136 + bc1) * 4u,
              Bw + (size_t)(k0 + br1) * N + bn + bc1);
    };

    issue(0); CP_COMMIT();
    issue(1); CP_COMMIT();
    issue(2); CP_COMMIT();

    for (int c = 0; c < NC; c++) {
        const int st = c & 3;
        CP_WAIT2();
        __syncthreads();

        if (c + 3 < NC) issue(c + 3);
        CP_COMMIT();

        const float* As = AsF + st * AS_STRIDE;
        const float* Bs = BsF + st * BS_STRIDE;
#pragma unroll
        for (int ks = 0; ks < 2; ks++) {
            const int kb = ks * 8;
            uint32_t af[2][4], bf[8][2];
#pragma unroll
            for (int mt = 0; mt < 2; mt++) {
                const int m = m0 + mt * 16 + g;
                af[mt][0] = tf32u(As[m * 20 + kb + t]);
                af[mt][1] = tf32u(As[(m + 8) * 20 + kb + t]);
                af[mt][2] = tf32u(As[m * 20 + kb + t + 4]);
                af[mt][3] = tf32u(As[(m + 8) * 20 + kb + t + 4]);
            }
#pragma unroll
            for (int nt = 0; nt < 8; nt++) {
                const int n = n0 + nt * 8 + g;
                bf[nt][0] = tf32u(Bs[(kb + t) * 136 + n]);
                bf[nt][1] = tf32u(Bs[(kb + t + 4) * 136 + n]);
            }
#pragma unroll
            for (int mt = 0; mt < 2; mt++)
#pragma unroll
                for (int nt = 0; nt < 8; nt++)
                    mma_tf32(acc[mt][nt][0], acc[mt][nt][1],
                             acc[mt][nt][2], acc[mt][nt][3],
                             af[mt][0], af[mt][1], af[mt][2], af[mt][3],
                             bf[nt][0], bf[nt][1]);
        }
    }

    const int ng = bn + n0;
    if (MODE == 0) {
        const int which = ng >> 10;
        const int rem   = ng & 1023;
        const int h     = rem >> 6;
#pragma unroll
        for (int mt = 0; mt < 2; mt++) {
            const int row0 = bm + m0 + mt * 16 + g;
            const int row1 = row0 + 8;
            const int b0i = row0 >> 11, t0i = row0 & 2047;
            const int b1i = row1 >> 11, t1i = row1 & 2047;
            float* base0 = g_qkv + ((size_t)((which * BB + b0i) * NH + h) * TT + t0i) * HD;
            float* base1 = g_qkv + ((size_t)((which * BB + b1i) * NH + h) * TT + t1i) * HD;
#pragma unroll
            for (int nt = 0; nt < 8; nt++) {
                const int d = nt * 8 + 2 * t;
                const float bx = bias[ng + d], by = bias[ng + d + 1];
                float2 o0 = { acc[mt][nt][0] + bx, acc[mt][nt][1] + by };
                float2 o1 = { acc[mt][nt][2] + bx, acc[mt][nt][3] + by };
                *(float2*)(base0 + d) = o0;
                *(float2*)(base1 + d) = o1;
            }
        }
    } else {
#pragma unroll
        for (int mt = 0; mt < 2; mt++) {
            const int row0 = bm + m0 + mt * 16 + g;
            const int row1 = row0 + 8;
#pragma unroll
            for (int nt = 0; nt < 8; nt++) {
                const int n = ng + nt * 8 + 2 * t;
                const float bx = bias[n], by = bias[n + 1];
                float2 o0 = { acc[mt][nt][0] + bx, acc[mt][nt][1] + by };
                float2 o1 = { acc[mt][nt][2] + bx, acc[mt][nt][3] + by };
                *(float2*)(C + (size_t)row0 * N + n) = o0;
                *(float2*)(C + (size_t)row1 * N + n) = o1;
            }
        }
    }
}

// ---------------------------------------------------------------------------
// Flash attention on tf32 mma.sync (exact R5 known-good version).
// ---------------------------------------------------------------------------
#define FLASH_SMEM ((2 * 64 * 68 + 128 * 68) * 4)

__global__ __launch_bounds__(256) void flash_mma()
{
    extern __shared__ float sm[];
    float* Ks = sm;                  // [64][68] tf32
    float* Vs = sm + 64 * 68;        // [64][68] tf32
    float* Ps = sm + 2 * 64 * 68;    // [128][68]: Q staging, then P (tf32)

    const int tid  = threadIdx.x;
    const int w    = tid >> 5;
    const int lane = tid & 31;
    const int g    = lane >> 2;
    const int t    = lane & 3;
    const int qt   = (int)gridDim.x - 1 - (int)blockIdx.x;
    const int h    = blockIdx.y;
    const int b    = blockIdx.z;
    const int q_base = qt * 128;
    const int mb     = w * 16;

    const float* Qg = g_qkv + ((size_t)((0 * BB + b) * NH + h) * TT) * HD;
    const float* Kg = g_qkv + ((size_t)((1 * BB + b) * NH + h) * TT) * HD;
    const float* Vg = g_qkv + ((size_t)((2 * BB + b) * NH + h) * TT) * HD;

    for (int i = tid; i < 2048; i += 256) {
        const int row = i >> 4, c4 = (i & 15) * 4;
        float4 v = *(const float4*)(Qg + (size_t)(q_base + row) * HD + c4);
        v.x = to_tf32(v.x * 0.125f);
        v.y = to_tf32(v.y * 0.125f);
        v.z = to_tf32(v.z * 0.125f);
        v.w = to_tf32(v.w * 0.125f);
        *(float4*)&Ps[row * 68 + c4] = v;
    }
    __syncthreads();

    uint32_t qa[8][4];
#pragma unroll
    for (int ks = 0; ks < 8; ks++) {
        const int kb = ks * 8;
        qa[ks][0] = __float_as_uint(Ps[(mb + g) * 68 + kb + t]);
        qa[ks][1] = __float_as_uint(Ps[(mb + g + 8) * 68 + kb + t]);
        qa[ks][2] = __float_as_uint(Ps[(mb + g) * 68 + kb + t + 4]);
        qa[ks][3] = __float_as_uint(Ps[(mb + g + 8) * 68 + kb + t + 4]);
    }

    float oacc[8][4];
#pragma unroll
    for (int nt = 0; nt < 8; nt++)
#pragma unroll
        for (int r = 0; r < 4; r++) oacc[nt][r] = 0.f;
    float m0 = -1e30f, m1 = -1e30f, l0 = 0.f, l1 = 0.f;
    const int r0 = q_base + mb + g, r1 = r0 + 8;

    const int nkt = 2 * qt + 2;
    for (int kt = 0; kt < nkt; kt++) {
        __syncthreads();
        const float* Kt = Kg + (size_t)(kt * 64) * HD;
        const float* Vt = Vg + (size_t)(kt * 64) * HD;
        for (int i = tid; i < 1024; i += 256) {
            const int row = i >> 4, c4 = (i & 15) * 4;
            float4 kv = *(const float4*)(Kt + row * HD + c4);
            kv.x = to_tf32(kv.x); kv.y = to_tf32(kv.y);
            kv.z = to_tf32(kv.z); kv.w = to_tf32(kv.w);
            *(float4*)&Ks[row * 68 + c4] = kv;
            float4 vv = *(const float4*)(Vt + row * HD + c4);
            vv.x = to_tf32(vv.x); vv.y = to_tf32(vv.y);
            vv.z = to_tf32(vv.z); vv.w = to_tf32(vv.w);
            *(float4*)&Vs[row * 68 + c4] = vv;
        }
        __syncthreads();

        float sacc[8][4];
#pragma unroll
        for (int nt = 0; nt < 8; nt++)
#pragma unroll
            for (int r = 0; r < 4; r++) sacc[nt][r] = 0.f;
#pragma unroll
        for (int ks = 0; ks < 8; ks++) {
            const int kb = ks * 8;
            uint32_t bf[8][2];
#pragma unroll
            for (int nt = 0; nt < 8; nt++) {
                bf[nt][0] = __float_as_uint(Ks[(nt * 8 + g) * 68 + kb + t]);
                bf[nt][1] = __float_as_uint(Ks[(nt * 8 + g) * 68 + kb + t + 4]);
            }
#pragma unroll
            for (int nt = 0; nt < 8; nt++)
                mma_tf32(sacc[nt][0], sacc[nt][1], sacc[nt][2], sacc[nt][3],
                         qa[ks][0], qa[ks][1], qa[ks][2], qa[ks][3],
                         bf[nt][0], bf[nt][1]);
        }

        if (kt >= 2 * qt) {
            const int sb = kt * 64;
#pragma unroll
            for (int nt = 0; nt < 8; nt++) {
                const int c0 = sb + nt * 8 + 2 * t, c1 = c0 + 1;
                if (c0 > r0) sacc[nt][0] = -1e30f;
                if (c1 > r0) sacc[nt][1] = -1e30f;
                if (c0 > r1) sacc[nt][2] = -1e30f;
                if (c1 > r1) sacc[nt][3] = -1e30f;
            }
        }

        float mx0 = -1e30f, mx1 = -1e30f;
#pragma unroll
        for (int nt = 0; nt < 8; nt++) {
            mx0 = fmaxf(mx0, fmaxf(sacc[nt][0], sacc[nt][1]));
            mx1 = fmaxf(mx1, fmaxf(sacc[nt][2], sacc[nt][3]));
        }
        mx0 = fmaxf(mx0, __shfl_xor_sync(0xffffffffu, mx0, 1));
        mx0 = fmaxf(mx0, __shfl_xor_sync(0xffffffffu, mx0, 2));
        mx1 = fmaxf(mx1, __shfl_xor_sync(0xffffffffu, mx1, 1));
        mx1 = fmaxf(mx1, __shfl_xor_sync(0xffffffffu, mx1, 2));

        const float mn0 = fmaxf(m0, mx0), mn1 = fmaxf(m1, mx1);
        const float f0 = __expf(m0 - mn0), f1 = __expf(m1 - mn1);
        float ls0 = 0.f, ls1 = 0.f;
#pragma unroll
        for (int nt = 0; nt < 8; nt++) {
            const float p00 = __expf(sacc[nt][0] - mn0);
            const float p01 = __expf(sacc[nt][1] - mn0);
            const float p10 = __expf(sacc[nt][2] - mn1);
            const float p11 = __expf(sacc[nt][3] - mn1);
            ls0 += p00 + p01;
            ls1 += p10 + p11;
            float2 s0 = { to_tf32(p00), to_tf32(p01) };
            float2 s1 = { to_tf32(p10), to_tf32(p11) };
            *(float2*)&Ps[(mb + g) * 68 + nt * 8 + 2 * t]     = s0;
            *(float2*)&Ps[(mb + g + 8) * 68 + nt * 8 + 2 * t] = s1;
        }
        ls0 += __shfl_xor_sync(0xffffffffu, ls0, 1);
        ls0 += __shfl_xor_sync(0xffffffffu, ls0, 2);
        ls1 += __shfl_xor_sync(0xffffffffu, ls1, 1);
        ls1 += __shfl_xor_sync(0xffffffffu, ls1, 2);
        l0 = l0 * f0 + ls0;
        l1 = l1 * f1 + ls1;
        m0 = mn0; m1 = mn1;
#pragma unroll
        for (int nt = 0; nt < 8; nt++) {
            oacc[nt][0] *= f0; oacc[nt][1] *= f0;
            oacc[nt][2] *= f1; oacc[nt][3] *= f1;
        }
        __syncwarp();

#pragma unroll
        for (int ks = 0; ks < 8; ks++) {
            const int kb = ks * 8;
            uint32_t pa[4];
            pa[0] = __float_as_uint(Ps[(mb + g) * 68 + kb + t]);
            pa[1] = __float_as_uint(Ps[(mb + g + 8) * 68 + kb + t]);
            pa[2] = __float_as_uint(Ps[(mb + g) * 68 + kb + t + 4]);
            pa[3] = __float_as_uint(Ps[(mb + g + 8) * 68 + kb + t + 4]);
            uint32_t bf[8][2];
#pragma unroll
            for (int nt = 0; nt < 8; nt++) {
                bf[nt][0] = __float_as_uint(Vs[(kb + t) * 68 + nt * 8 + g]);
                bf[nt][1] = __float_as_uint(Vs[(kb + t + 4) * 68 + nt * 8 + g]);
            }
#pragma unroll
            for (int nt = 0; nt < 8; nt++)
                mma_tf32(oacc[nt][0], oacc[nt][1], oacc[nt][2], oacc[nt][3],
                         pa[0], pa[1], pa[2], pa[3], bf[nt][0], bf[nt][1]);
        }
    }

    const float i0 = 1.0f / l0, i1 = 1.0f / l1;
    float* O0 = g_att + ((size_t)(b * TT + r0) * NH + h) * HD;
    float* O1 = g_att + ((size_t)(b * TT + r1) * NH + h) * HD;
#pragma unroll
    for (int nt = 0; nt < 8; nt++) {
        const int d = nt * 8 + 2 * t;
        float2 o0 = { oacc[nt][0] * i0, oacc[nt][1] * i0 };
        float2 o1 = { oacc[nt][2] * i1, oacc[nt][3] * i1 };
        *(float2*)(O0 + d) = o0;
        *(float2*)(O1 + d) = o1;
    }
}

// ---------------------------------------------------------------------------
// kernel_launch
// ---------------------------------------------------------------------------
extern "C" void kernel_launch(void* const* d_in, const int* in_sizes, int n_in,
                              void* d_out, int out_size)
{
    const float* x      = (const float*)d_in[0];
    const float* w_qkv  = (const float*)d_in[1];
    const float* b_qkv  = (const float*)d_in[2];
    const float* w_proj = (const float*)d_in[3];
    const float* b_proj = (const float*)d_in[4];
    float* out = (float*)d_out;

    const int M = BB * TT;  // 4096

    cudaFuncSetAttribute(mma_gemm<0>, cudaFuncAttributeMaxDynamicSharedMemorySize, GSMEM_BYTES);
    cudaFuncSetAttribute(mma_gemm<1>, cudaFuncAttributeMaxDynamicSharedMemorySize, GSMEM_BYTES);
    cudaFuncSetAttribute(flash_mma, cudaFuncAttributeMaxDynamicSharedMemorySize, FLASH_SMEM);

    // 1) QKV projection (tf32 mma.sync + cp.async pipeline) -> g_qkv
    mma_gemm<0><<<dim3(3 * DM / 128, M / 128), 256, GSMEM_BYTES>>>(x, w_qkv, b_qkv, nullptr, M, 3 * DM, DM);

    // 2) causal flash attention (tf32 mma.sync) -> g_att
    flash_mma<<<dim3(TT / 128, NH, BB), 256, FLASH_SMEM>>>();

    // 3) output projection (tf32 mma.sync + cp.async pipeline) -> out
    mma_gemm<1><<<dim3(DM / 128, M / 128), 256, GSMEM_BYTES>>>(nullptr, w_proj, b_proj, out, M, DM, DM);
}

// round 8
// speedup vs baseline: 1.7172x; 1.0870x over previous
#include <cuda_runtime.h>
#include <cstdint>

// Problem constants
#define DM   1024
#define NH   16
#define HD   64
#define BB   2
#define TT   2048

// Scratch (device globals: allocation-free rule)
__device__ float g_qkv[3 * BB * NH * TT * HD];   // [which][b][h][t][d], tf32-rounded
__device__ float g_att[BB * TT * DM];            // [b][t][h][d], tf32-rounded
__device__ float g_xr[BB * TT * DM];             // x, tf32-rounded
__device__ float g_wqr[DM * 3 * DM];             // w_qkv, tf32-rounded
__device__ float g_wpr[DM * DM];                 // w_proj, tf32-rounded

// ---------------------------------------------------------------------------
// tf32 helpers (portable PTX: works on plain sm_103 target)
// ---------------------------------------------------------------------------
__device__ __forceinline__ float to_tf32(float x) {
    uint32_t u;
    asm("cvt.rna.tf32.f32 %0, %1;" : "=r"(u) : "f"(x));
    return __uint_as_float(u);
}

__device__ __forceinline__ void mma_tf32(float& c0, float& c1, float& c2, float& c3,
                                         uint32_t a0, uint32_t a1, uint32_t a2, uint32_t a3,
                                         uint32_t b0, uint32_t b1) {
    asm volatile(
        "mma.sync.aligned.m16n8k8.row.col.f32.tf32.tf32.f32 "
        "{%0,%1,%2,%3}, {%4,%5,%6,%7}, {%8,%9}, {%0,%1,%2,%3};"
        : "+f"(c0), "+f"(c1), "+f"(c2), "+f"(c3)
        : "r"(a0), "r"(a1), "r"(a2), "r"(a3), "r"(b0), "r"(b1));
}

__device__ __forceinline__ uint32_t smem_u32(const void* p) {
    uint32_t a;
    asm("{ .reg .u64 t; cvta.to.shared.u64 t, %1; cvt.u32.u64 %0, t; }"
        : "=r"(a) : "l"(p));
    return a;
}
__device__ __forceinline__ void cpa16(uint32_t saddr, const void* g) {
    asm volatile("cp.async.cg.shared.global [%0], [%1], 16;"
                 :: "r"(saddr), "l"(g) : "memory");
}
#define CP_COMMIT() asm volatile("cp.async.commit_group;" ::: "memory")
#define CP_WAIT2()  asm volatile("cp.async.wait_group 2;" ::: "memory")
#define CP_WAIT0()  asm volatile("cp.async.wait_group 0;" ::: "memory")

// ---------------------------------------------------------------------------
// Prepass: tf32-round an array (float4 grid-stride)
// ---------------------------------------------------------------------------
__global__ __launch_bounds__(256) void round_k(const float* __restrict__ src,
                                               float* __restrict__ dst, int n4)
{
    const int stride = gridDim.x * blockDim.x;
    for (int i = blockIdx.x * blockDim.x + threadIdx.x; i < n4; i += stride) {
        float4 v = *(const float4*)(src + (size_t)i * 4);
        v.x = to_tf32(v.x); v.y = to_tf32(v.y);
        v.z = to_tf32(v.z); v.w = to_tf32(v.w);
        *(float4*)(dst + (size_t)i * 4) = v;
    }
}

// ---------------------------------------------------------------------------
// tf32 tensor-core GEMM, 4-stage cp.async pipeline, pre-rounded inputs
// (no cvt in the hot loop).  BM=BN=128, BK=16, 8 warps (32x64 each).
// MODE 0: A=g_xr, epilogue writes tf32-rounded(acc+bias) scattered to g_qkv.
// MODE 1: A=g_att (pre-rounded), epilogue writes plain fp32 C.
// ---------------------------------------------------------------------------
#define AS_STRIDE (128 * 20)
#define BS_STRIDE (16 * 136)
#define GSMEM_BYTES ((4 * AS_STRIDE + 4 * BS_STRIDE) * 4)

template <int MODE>
__global__ __launch_bounds__(256) void mma_gemm(const float* __restrict__ bias,
                                                float* __restrict__ C,
                                                int M, int N, int K)
{
    extern __shared__ float dsm[];
    float* AsF = dsm;
    float* BsF = dsm + 4 * AS_STRIDE;
    const uint32_t abase = smem_u32(AsF);
    const uint32_t bbase = smem_u32(BsF);

    const int tid  = threadIdx.x;
    const int bm   = blockIdx.y * 128;
    const int bn   = blockIdx.x * 128;
    const int w    = tid >> 5;
    const int lane = tid & 31;
    const int g    = lane >> 2;
    const int t    = lane & 3;
    const int m0   = (w & 3) * 32;
    const int n0   = (w >> 2) * 64;

    const float* Aeff = (MODE == 0) ? (const float*)g_xr : (const float*)g_att;
    const float* Bw   = (MODE == 0) ? (const float*)g_wqr : (const float*)g_wpr;

    float acc[2][8][4];
#pragma unroll
    for (int mt = 0; mt < 2; mt++)
#pragma unroll
        for (int nt = 0; nt < 8; nt++)
#pragma unroll
            for (int r = 0; r < 4; r++) acc[mt][nt][r] = 0.f;

    const int av0 = tid,        av1 = tid + 256;
    const int ar0 = av0 >> 2,   ac0 = (av0 & 3) * 4;
    const int ar1 = av1 >> 2,   ac1 = (av1 & 3) * 4;
    const int br0 = av0 >> 5,   bc0 = (av0 & 31) * 4;
    const int br1 = av1 >> 5,   bc1 = (av1 & 31) * 4;

    const int NC = K >> 4;

    auto issue = [&](int c) {
        const int s = c & 3;
        const uint32_t as = abase + (uint32_t)(s * AS_STRIDE) * 4u;
        const uint32_t bs = bbase + (uint32_t)(s * BS_STRIDE) * 4u;
        const int k0 = c << 4;
        cpa16(as + (uint32_t)(ar0 * 20 + ac0) * 4u,
              Aeff + (size_t)(bm + ar0) * K + k0 + ac0);
        cpa16(as + (uint32_t)(ar1 * 20 + ac1) * 4u,
              Aeff + (size_t)(bm + ar1) * K + k0 + ac1);
        cpa16(bs + (uint32_t)(br0 * 136 + bc0) * 4u,
              Bw + (size_t)(k0 + br0) * N + bn + bc0);
        cpa16(bs + (uint32_t)(br1 * 136 + bc1) * 4u,
              Bw + (size_t)(k0 + br1) * N + bn + bc1);
    };

    issue(0); CP_COMMIT();
    issue(1); CP_COMMIT();
    issue(2); CP_COMMIT();

    for (int c = 0; c < NC; c++) {
        const int st = c & 3;
        CP_WAIT2();
        __syncthreads();

        if (c + 3 < NC) issue(c + 3);
        CP_COMMIT();

        const float* As = AsF + st * AS_STRIDE;
        const float* Bs = BsF + st * BS_STRIDE;
#pragma unroll
        for (int ks = 0; ks < 2; ks++) {
            const int kb = ks * 8;
            uint32_t af[2][4], bf[8][2];
#pragma unroll
            for (int mt = 0; mt < 2; mt++) {
                const int m = m0 + mt * 16 + g;
                af[mt][0] = __float_as_uint(As[m * 20 + kb + t]);
                af[mt][1] = __float_as_uint(As[(m + 8) * 20 + kb + t]);
                af[mt][2] = __float_as_uint(As[m * 20 + kb + t + 4]);
                af[mt][3] = __float_as_uint(As[(m + 8) * 20 + kb + t + 4]);
            }
#pragma unroll
            for (int nt = 0; nt < 8; nt++) {
                const int n = n0 + nt * 8 + g;
                bf[nt][0] = __float_as_uint(Bs[(kb + t) * 136 + n]);
                bf[nt][1] = __float_as_uint(Bs[(kb + t + 4) * 136 + n]);
            }
#pragma unroll
            for (int mt = 0; mt < 2; mt++)
#pragma unroll
                for (int nt = 0; nt < 8; nt++)
                    mma_tf32(acc[mt][nt][0], acc[mt][nt][1],
                             acc[mt][nt][2], acc[mt][nt][3],
                             af[mt][0], af[mt][1], af[mt][2], af[mt][3],
                             bf[nt][0], bf[nt][1]);
        }
    }

    const int ng = bn + n0;
    if (MODE == 0) {
        const int which = ng >> 10;
        const int rem   = ng & 1023;
        const int h     = rem >> 6;
#pragma unroll
        for (int mt = 0; mt < 2; mt++) {
            const int row0 = bm + m0 + mt * 16 + g;
            const int row1 = row0 + 8;
            const int b0i = row0 >> 11, t0i = row0 & 2047;
            const int b1i = row1 >> 11, t1i = row1 & 2047;
            float* base0 = g_qkv + ((size_t)((which * BB + b0i) * NH + h) * TT + t0i) * HD;
            float* base1 = g_qkv + ((size_t)((which * BB + b1i) * NH + h) * TT + t1i) * HD;
#pragma unroll
            for (int nt = 0; nt < 8; nt++) {
                const int d = nt * 8 + 2 * t;
                const float bx = bias[ng + d], by = bias[ng + d + 1];
                float2 o0 = { to_tf32(acc[mt][nt][0] + bx), to_tf32(acc[mt][nt][1] + by) };
                float2 o1 = { to_tf32(acc[mt][nt][2] + bx), to_tf32(acc[mt][nt][3] + by) };
                *(float2*)(base0 + d) = o0;
                *(float2*)(base1 + d) = o1;
            }
        }
    } else {
#pragma unroll
        for (int mt = 0; mt < 2; mt++) {
            const int row0 = bm + m0 + mt * 16 + g;
            const int row1 = row0 + 8;
#pragma unroll
            for (int nt = 0; nt < 8; nt++) {
                const int n = ng + nt * 8 + 2 * t;
                const float bx = bias[n], by = bias[n + 1];
                float2 o0 = { acc[mt][nt][0] + bx, acc[mt][nt][1] + by };
                float2 o1 = { acc[mt][nt][2] + bx, acc[mt][nt][3] + by };
                *(float2*)(C + (size_t)row0 * N + n) = o0;
                *(float2*)(C + (size_t)row1 * N + n) = o1;
            }
        }
    }
}

// ---------------------------------------------------------------------------
// Flash attention, tf32 mma.sync. Inputs pre-rounded (g_qkv) -> NO cvts in
// staging. K/V via 2-stage cp.async double buffer (raw copy, no fixup).
// ---------------------------------------------------------------------------
#define FL_TILE  (64 * 68)
#define FLASH_SMEM ((4 * FL_TILE + 128 * 68) * 4)

__global__ __launch_bounds__(256, 2) void flash_mma()
{
    extern __shared__ float sm[];
    float* Ps = sm + 4 * FL_TILE;    // [128][68]: Q staging, then P (tf32)
    const uint32_t smb = smem_u32(sm);

    const int tid  = threadIdx.x;
    const int w    = tid >> 5;
    const int lane = tid & 31;
    const int g    = lane >> 2;
    const int t    = lane & 3;
    const int qt   = (int)gridDim.x - 1 - (int)blockIdx.x;  // heavy CTAs first
    const int h    = blockIdx.y;
    const int b    = blockIdx.z;
    const int q_base = qt * 128;
    const int mb     = w * 16;

    const float* Qg = g_qkv + ((size_t)((0 * BB + b) * NH + h) * TT) * HD;
    const float* Kg = g_qkv + ((size_t)((1 * BB + b) * NH + h) * TT) * HD;
    const float* Vg = g_qkv + ((size_t)((2 * BB + b) * NH + h) * TT) * HD;

    int frow[4], fc4[4];
#pragma unroll
    for (int j = 0; j < 4; j++) {
        const int v = tid + 256 * j;
        frow[j] = v >> 4;
        fc4[j]  = (v & 15) * 4;
    }

    auto issue_kv = [&](int kt) {
        const int s = kt & 1;
        const uint32_t kb = smb + (uint32_t)(s * 2 * FL_TILE) * 4u;
        const uint32_t vb = kb + (uint32_t)FL_TILE * 4u;
        const float* Kt = Kg + (size_t)(kt * 64) * HD;
        const float* Vt = Vg + (size_t)(kt * 64) * HD;
#pragma unroll
        for (int j = 0; j < 4; j++) {
            const uint32_t so = (uint32_t)(frow[j] * 68 + fc4[j]) * 4u;
            const size_t   go = (size_t)frow[j] * HD + fc4[j];
            cpa16(kb + so, Kt + go);
            cpa16(vb + so, Vt + go);
        }
    };

    issue_kv(0); CP_COMMIT();

    // stage Q tile (data already tf32; *0.125 is exact -> stays tf32)
    for (int i = tid; i < 2048; i += 256) {
        const int row = i >> 4, c4 = (i & 15) * 4;
        float4 v = *(const float4*)(Qg + (size_t)(q_base + row) * HD + c4);
        v.x *= 0.125f; v.y *= 0.125f; v.z *= 0.125f; v.w *= 0.125f;
        *(float4*)&Ps[row * 68 + c4] = v;
    }
    __syncthreads();

    uint32_t qa[8][4];
#pragma unroll
    for (int ks = 0; ks < 8; ks++) {
        const int kb = ks * 8;
        qa[ks][0] = __float_as_uint(Ps[(mb + g) * 68 + kb + t]);
        qa[ks][1] = __float_as_uint(Ps[(mb + g + 8) * 68 + kb + t]);
        qa[ks][2] = __float_as_uint(Ps[(mb + g) * 68 + kb + t + 4]);
        qa[ks][3] = __float_as_uint(Ps[(mb + g + 8) * 68 + kb + t + 4]);
    }

    float oacc[8][4];
#pragma unroll
    for (int nt = 0; nt < 8; nt++)
#pragma unroll
        for (int r = 0; r < 4; r++) oacc[nt][r] = 0.f;
    float m0 = -1e30f, m1 = -1e30f, l0 = 0.f, l1 = 0.f;
    const int r0 = q_base + mb + g, r1 = r0 + 8;

    const int nkt = 2 * qt + 2;
    for (int kt = 0; kt < nkt; kt++) {
        const int st = kt & 1;
        float* Ks = sm + st * 2 * FL_TILE;
        float* Vs = Ks + FL_TILE;

        CP_WAIT0();
        __syncthreads();   // tile kt visible; all warps done with stage st^1

        if (kt + 1 < nkt) issue_kv(kt + 1);
        CP_COMMIT();

        // S = Q @ K^T   (16x64 per warp)
        float sacc[8][4];
#pragma unroll
        for (int nt = 0; nt < 8; nt++)
#pragma unroll
            for (int r = 0; r < 4; r++) sacc[nt][r] = 0.f;
#pragma unroll
        for (int ks = 0; ks < 8; ks++) {
            const int kb = ks * 8;
            uint32_t bf[8][2];
#pragma unroll
            for (int nt = 0; nt < 8; nt++) {
                bf[nt][0] = __float_as_uint(Ks[(nt * 8 + g) * 68 + kb + t]);
                bf[nt][1] = __float_as_uint(Ks[(nt * 8 + g) * 68 + kb + t + 4]);
            }
#pragma unroll
            for (int nt = 0; nt < 8; nt++)
                mma_tf32(sacc[nt][0], sacc[nt][1], sacc[nt][2], sacc[nt][3],
                         qa[ks][0], qa[ks][1], qa[ks][2], qa[ks][3],
                         bf[nt][0], bf[nt][1]);
        }

        if (kt >= 2 * qt) {
            const int sb = kt * 64;
#pragma unroll
            for (int nt = 0; nt < 8; nt++) {
                const int c0 = sb + nt * 8 + 2 * t, c1 = c0 + 1;
                if (c0 > r0) sacc[nt][0] = -1e30f;
                if (c1 > r0) sacc[nt][1] = -1e30f;
                if (c0 > r1) sacc[nt][2] = -1e30f;
                if (c1 > r1) sacc[nt][3] = -1e30f;
            }
        }

        float mx0 = -1e30f, mx1 = -1e30f;
#pragma unroll
        for (int nt = 0; nt < 8; nt++) {
            mx0 = fmaxf(mx0, fmaxf(sacc[nt][0], sacc[nt][1]));
            mx1 = fmaxf(mx1, fmaxf(sacc[nt][2], sacc[nt][3]));
        }
        mx0 = fmaxf(mx0, __shfl_xor_sync(0xffffffffu, mx0, 1));
        mx0 = fmaxf(mx0, __shfl_xor_sync(0xffffffffu, mx0, 2));
        mx1 = fmaxf(mx1, __shfl_xor_sync(0xffffffffu, mx1, 1));
        mx1 = fmaxf(mx1, __shfl_xor_sync(0xffffffffu, mx1, 2));

        const float mn0 = fmaxf(m0, mx0), mn1 = fmaxf(m1, mx1);
        const float f0 = __expf(m0 - mn0), f1 = __expf(m1 - mn1);
        float ls0 = 0.f, ls1 = 0.f;
#pragma unroll
        for (int nt = 0; nt < 8; nt++) {
            const float p00 = __expf(sacc[nt][0] - mn0);
            const float p01 = __expf(sacc[nt][1] - mn0);
            const float p10 = __expf(sacc[nt][2] - mn1);
            const float p11 = __expf(sacc[nt][3] - mn1);
            ls0 += p00 + p01;
            ls1 += p10 + p11;
            float2 s0 = { to_tf32(p00), to_tf32(p01) };
            float2 s1 = { to_tf32(p10), to_tf32(p11) };
            *(float2*)&Ps[(mb + g) * 68 + nt * 8 + 2 * t]     = s0;
            *(float2*)&Ps[(mb + g + 8) * 68 + nt * 8 + 2 * t] = s1;
        }
        ls0 += __shfl_xor_sync(0xffffffffu, ls0, 1);
        ls0 += __shfl_xor_sync(0xffffffffu, ls0, 2);
        ls1 += __shfl_xor_sync(0xffffffffu, ls1, 1);
        ls1 += __shfl_xor_sync(0xffffffffu, ls1, 2);
        l0 = l0 * f0 + ls0;
        l1 = l1 * f1 + ls1;
        m0 = mn0; m1 = mn1;
#pragma unroll
        for (int nt = 0; nt < 8; nt++) {
            oacc[nt][0] *= f0; oacc[nt][1] *= f0;
            oacc[nt][2] *= f1; oacc[nt][3] *= f1;
        }
        __syncwarp();   // P rows are private to this warp

        // O += P @ V
#pragma unroll
        for (int ks = 0; ks < 8; ks++) {
            const int kb = ks * 8;
            uint32_t pa[4];
            pa[0] = __float_as_uint(Ps[(mb + g) * 68 + kb + t]);
            pa[1] = __float_as_uint(Ps[(mb + g + 8) * 68 + kb + t]);
            pa[2] = __float_as_uint(Ps[(mb + g) * 68 + kb + t + 4]);
            pa[3] = __float_as_uint(Ps[(mb + g + 8) * 68 + kb + t + 4]);
            uint32_t bf[8][2];
#pragma unroll
            for (int nt = 0; nt < 8; nt++) {
                bf[nt][0] = __float_as_uint(Vs[(kb + t) * 68 + nt * 8 + g]);
                bf[nt][1] = __float_as_uint(Vs[(kb + t + 4) * 68 + nt * 8 + g]);
            }
#pragma unroll
            for (int nt = 0; nt < 8; nt++)
                mma_tf32(oacc[nt][0], oacc[nt][1], oacc[nt][2], oacc[nt][3],
                         pa[0], pa[1], pa[2], pa[3], bf[nt][0], bf[nt][1]);
        }
    }

    // epilogue: tf32-round (proj GEMM rounds anyway -> identical numerics)
    const float i0 = 1.0f / l0, i1 = 1.0f / l1;
    float* O0 = g_att + ((size_t)(b * TT + r0) * NH + h) * HD;
    float* O1 = g_att + ((size_t)(b * TT + r1) * NH + h) * HD;
#pragma unroll
    for (int nt = 0; nt < 8; nt++) {
        const int d = nt * 8 + 2 * t;
        float2 o0 = { to_tf32(oacc[nt][0] * i0), to_tf32(oacc[nt][1] * i0) };
        float2 o1 = { to_tf32(oacc[nt][2] * i1), to_tf32(oacc[nt][3] * i1) };
        *(float2*)(O0 + d) = o0;
        *(float2*)(O1 + d) = o1;
    }
}

// ---------------------------------------------------------------------------
// kernel_launch
// ---------------------------------------------------------------------------
extern "C" void kernel_launch(void* const* d_in, const int* in_sizes, int n_in,
                              void* d_out, int out_size)
{
    const float* x      = (const float*)d_in[0];
    const float* w_qkv  = (const float*)d_in[1];
    const float* b_qkv  = (const float*)d_in[2];
    const float* w_proj = (const float*)d_in[3];
    const float* b_proj = (const float*)d_in[4];
    float* out = (float*)d_out;

    const int M = BB * TT;  // 4096

    cudaFuncSetAttribute(mma_gemm<0>, cudaFuncAttributeMaxDynamicSharedMemorySize, GSMEM_BYTES);
    cudaFuncSetAttribute(mma_gemm<1>, cudaFuncAttributeMaxDynamicSharedMemorySize, GSMEM_BYTES);
    cudaFuncSetAttribute(flash_mma, cudaFuncAttributeMaxDynamicSharedMemorySize, FLASH_SMEM);

    float* d_xr  = nullptr; cudaGetSymbolAddress((void**)&d_xr,  g_xr);
    float* d_wqr = nullptr; cudaGetSymbolAddress((void**)&d_wqr, g_wqr);
    float* d_wpr = nullptr; cudaGetSymbolAddress((void**)&d_wpr, g_wpr);

    // 0) prepass: tf32-round inputs (numerically identical to rounding at use)
    round_k<<<512, 256>>>(x,      d_xr,  BB * TT * DM / 4);
    round_k<<<512, 256>>>(w_qkv,  d_wqr, DM * 3 * DM / 4);
    round_k<<<512, 256>>>(w_proj, d_wpr, DM * DM / 4);

    // 1) QKV projection (tf32 mma.sync, cp.async, no hot-loop cvt) -> g_qkv
    mma_gemm<0><<<dim3(3 * DM / 128, M / 128), 256, GSMEM_BYTES>>>(b_qkv, nullptr, M, 3 * DM, DM);

    // 2) causal flash attention (tf32 mma.sync, cp.async K/V) -> g_att
    flash_mma<<<dim3(TT / 128, NH, BB), 256, FLASH_SMEM>>>();

    // 3) output projection -> out
    mma_gemm<1><<<dim3(DM / 128, M / 128), 256, GSMEM_BYTES>>>(b_proj, out, M, DM, DM);
}

// round 9
// speedup vs baseline: 2.0091x; 1.1700x over previous
#include <cuda_runtime.h>
#include <cstdint>

// Problem constants
#define DM   1024
#define NH   16
#define HD   64
#define BB   2
#define TT   2048

// Scratch (device globals: allocation-free rule)
__device__ float g_qkv[3 * BB * NH * TT * HD];   // [which][b][h][t][d], tf32-rounded
__device__ float g_att[BB * TT * DM];            // [b][t][h][d], tf32-rounded
__device__ float g_xr[BB * TT * DM];             // x, tf32-rounded
__device__ float g_wqr[DM * 3 * DM];             // w_qkv, tf32-rounded
__device__ float g_wpr[DM * DM];                 // w_proj, tf32-rounded

// ---------------------------------------------------------------------------
// tf32 helpers (portable PTX: works on plain sm_103 target)
// ---------------------------------------------------------------------------
__device__ __forceinline__ float to_tf32(float x) {
    uint32_t u;
    asm("cvt.rna.tf32.f32 %0, %1;" : "=r"(u) : "f"(x));
    return __uint_as_float(u);
}

__device__ __forceinline__ void mma_tf32(float& c0, float& c1, float& c2, float& c3,
                                         uint32_t a0, uint32_t a1, uint32_t a2, uint32_t a3,
                                         uint32_t b0, uint32_t b1) {
    asm volatile(
        "mma.sync.aligned.m16n8k8.row.col.f32.tf32.tf32.f32 "
        "{%0,%1,%2,%3}, {%4,%5,%6,%7}, {%8,%9}, {%0,%1,%2,%3};"
        : "+f"(c0), "+f"(c1), "+f"(c2), "+f"(c3)
        : "r"(a0), "r"(a1), "r"(a2), "r"(a3), "r"(b0), "r"(b1));
}

__device__ __forceinline__ uint32_t smem_u32(const void* p) {
    uint32_t a;
    asm("{ .reg .u64 t; cvta.to.shared.u64 t, %1; cvt.u32.u64 %0, t; }"
        : "=r"(a) : "l"(p));
    return a;
}
__device__ __forceinline__ void cpa16(uint32_t saddr, const void* g) {
    asm volatile("cp.async.cg.shared.global [%0], [%1], 16;"
                 :: "r"(saddr), "l"(g) : "memory");
}
#define CP_COMMIT() asm volatile("cp.async.commit_group;" ::: "memory")
#define CP_WAIT1()  asm volatile("cp.async.wait_group 1;" ::: "memory")
#define CP_WAIT0()  asm volatile("cp.async.wait_group 0;" ::: "memory")

// ---------------------------------------------------------------------------
// Prepass: tf32-round an array (float4 grid-stride)
// ---------------------------------------------------------------------------
__global__ __launch_bounds__(256) void round_k(const float* __restrict__ src,
                                               float* __restrict__ dst, int n4)
{
    const int stride = gridDim.x * blockDim.x;
    for (int i = blockIdx.x * blockDim.x + threadIdx.x; i < n4; i += stride) {
        float4 v = *(const float4*)(src + (size_t)i * 4);
        v.x = to_tf32(v.x); v.y = to_tf32(v.y);
        v.z = to_tf32(v.z); v.w = to_tf32(v.w);
        *(float4*)(dst + (size_t)i * 4) = v;
    }
}

// ---------------------------------------------------------------------------
// tf32 tensor-core GEMM, BK=32, 3-stage cp.async pipeline, pre-rounded
// inputs.  BM=BN=128, 8 warps (32x64 each), 128 MMAs per barrier window.
// A stage [128][36] (bank = 4m+t, conflict-free), B stage [32][136].
// MODE 0: A=g_xr, epilogue writes tf32(acc+bias) scattered to g_qkv.
// MODE 1: A=g_att, epilogue writes plain fp32 C.
// ---------------------------------------------------------------------------
#define AS_STRIDE (128 * 36)
#define BS_STRIDE (32 * 136)
#define GSMEM_BYTES ((3 * AS_STRIDE + 3 * BS_STRIDE) * 4)

template <int MODE>
__global__ __launch_bounds__(256) void mma_gemm(const float* __restrict__ bias,
                                                float* __restrict__ C,
                                                int M, int N, int K)
{
    extern __shared__ float dsm[];
    float* AsF = dsm;
    float* BsF = dsm + 3 * AS_STRIDE;
    const uint32_t abase = smem_u32(AsF);
    const uint32_t bbase = smem_u32(BsF);

    const int tid  = threadIdx.x;
    const int bm   = blockIdx.y * 128;
    const int bn   = blockIdx.x * 128;
    const int w    = tid >> 5;
    const int lane = tid & 31;
    const int g    = lane >> 2;
    const int t    = lane & 3;
    const int m0   = (w & 3) * 32;
    const int n0   = (w >> 2) * 64;

    const float* Aeff = (MODE == 0) ? (const float*)g_xr : (const float*)g_att;
    const float* Bw   = (MODE == 0) ? (const float*)g_wqr : (const float*)g_wpr;

    float acc[2][8][4];
#pragma unroll
    for (int mt = 0; mt < 2; mt++)
#pragma unroll
        for (int nt = 0; nt < 8; nt++)
#pragma unroll
            for (int r = 0; r < 4; r++) acc[mt][nt][r] = 0.f;

    // copy indexing: A chunk 128x32 = 1024 f4 (4/thread), B chunk 32x128 same
    int arow[4], ac4[4], brow[4], bc4[4];
#pragma unroll
    for (int j = 0; j < 4; j++) {
        const int f = tid + 256 * j;
        arow[j] = f >> 3;  ac4[j] = (f & 7) * 4;
        brow[j] = f >> 5;  bc4[j] = (f & 31) * 4;
    }

    const int NC = K >> 5;   // 32

    auto issue = [&](int c) {
        const int s = c % 3;
        const uint32_t as = abase + (uint32_t)(s * AS_STRIDE) * 4u;
        const uint32_t bs = bbase + (uint32_t)(s * BS_STRIDE) * 4u;
        const int k0 = c << 5;
#pragma unroll
        for (int j = 0; j < 4; j++) {
            cpa16(as + (uint32_t)(arow[j] * 36 + ac4[j]) * 4u,
                  Aeff + (size_t)(bm + arow[j]) * K + k0 + ac4[j]);
            cpa16(bs + (uint32_t)(brow[j] * 136 + bc4[j]) * 4u,
                  Bw + (size_t)(k0 + brow[j]) * N + bn + bc4[j]);
        }
    };

    issue(0); CP_COMMIT();
    issue(1); CP_COMMIT();

    for (int c = 0; c < NC; c++) {
        const int st = c % 3;
        CP_WAIT1();
        __syncthreads();          // chunk c visible; stage (c-1)%3 free

        if (c + 2 < NC) issue(c + 2);
        CP_COMMIT();

        const float* As = AsF + st * AS_STRIDE;
        const float* Bs = BsF + st * BS_STRIDE;
#pragma unroll
        for (int ks = 0; ks < 4; ks++) {
            const int kb = ks * 8;
            uint32_t af[2][4], bf[8][2];
#pragma unroll
            for (int mt = 0; mt < 2; mt++) {
                const int m = m0 + mt * 16 + g;
                af[mt][0] = __float_as_uint(As[m * 36 + kb + t]);
                af[mt][1] = __float_as_uint(As[(m + 8) * 36 + kb + t]);
                af[mt][2] = __float_as_uint(As[m * 36 + kb + t + 4]);
                af[mt][3] = __float_as_uint(As[(m + 8) * 36 + kb + t + 4]);
            }
#pragma unroll
            for (int nt = 0; nt < 8; nt++) {
                const int n = n0 + nt * 8 + g;
                bf[nt][0] = __float_as_uint(Bs[(kb + t) * 136 + n]);
                bf[nt][1] = __float_as_uint(Bs[(kb + t + 4) * 136 + n]);
            }
#pragma unroll
            for (int mt = 0; mt < 2; mt++)
#pragma unroll
                for (int nt = 0; nt < 8; nt++)
                    mma_tf32(acc[mt][nt][0], acc[mt][nt][1],
                             acc[mt][nt][2], acc[mt][nt][3],
                             af[mt][0], af[mt][1], af[mt][2], af[mt][3],
                             bf[nt][0], bf[nt][1]);
        }
    }

    const int ng = bn + n0;
    if (MODE == 0) {
        const int which = ng >> 10;
        const int rem   = ng & 1023;
        const int h     = rem >> 6;
#pragma unroll
        for (int mt = 0; mt < 2; mt++) {
            const int row0 = bm + m0 + mt * 16 + g;
            const int row1 = row0 + 8;
            const int b0i = row0 >> 11, t0i = row0 & 2047;
            const int b1i = row1 >> 11, t1i = row1 & 2047;
            float* base0 = g_qkv + ((size_t)((which * BB + b0i) * NH + h) * TT + t0i) * HD;
            float* base1 = g_qkv + ((size_t)((which * BB + b1i) * NH + h) * TT + t1i) * HD;
#pragma unroll
            for (int nt = 0; nt < 8; nt++) {
                const int d = nt * 8 + 2 * t;
                const float bx = bias[ng + d], by = bias[ng + d + 1];
                float2 o0 = { to_tf32(acc[mt][nt][0] + bx), to_tf32(acc[mt][nt][1] + by) };
                float2 o1 = { to_tf32(acc[mt][nt][2] + bx), to_tf32(acc[mt][nt][3] + by) };
                *(float2*)(base0 + d) = o0;
                *(float2*)(base1 + d) = o1;
            }
        }
    } else {
#pragma unroll
        for (int mt = 0; mt < 2; mt++) {
            const int row0 = bm + m0 + mt * 16 + g;
            const int row1 = row0 + 8;
#pragma unroll
            for (int nt = 0; nt < 8; nt++) {
                const int n = ng + nt * 8 + 2 * t;
                const float bx = bias[n], by = bias[n + 1];
                float2 o0 = { acc[mt][nt][0] + bx, acc[mt][nt][1] + by };
                float2 o1 = { acc[mt][nt][2] + bx, acc[mt][nt][3] + by };
                *(float2*)(C + (size_t)row0 * N + n) = o0;
                *(float2*)(C + (size_t)row1 * N + n) = o1;
            }
        }
    }
}

// ---------------------------------------------------------------------------
// Flash attention, tf32 mma.sync, pre-rounded inputs, 2-stage cp.async K/V.
// V buffer stride 72 (bank = 8t+g, conflict-free for PV fragment loads);
// K and P keep stride 68 (bank = 4row+col, conflict-free).
// ---------------------------------------------------------------------------
#define FK_TILE  (64 * 68)
#define FV_TILE  (64 * 72)
#define FLASH_SMEM ((2 * FK_TILE + 2 * FV_TILE + 128 * 68) * 4)

__global__ __launch_bounds__(256, 2) void flash_mma()
{
    extern __shared__ float sm[];
    // [0]            : K stage 0   (64x68)
    // [FK_TILE]      : K stage 1
    // [2*FK_TILE]    : V stage 0   (64x72)
    // [2*FK+FV]      : V stage 1
    float* Vb = sm + 2 * FK_TILE;
    float* Ps = sm + 2 * FK_TILE + 2 * FV_TILE;    // [128][68]: Q staging, then P
    const uint32_t smb = smem_u32(sm);
    const uint32_t vmb = smem_u32(Vb);

    const int tid  = threadIdx.x;
    const int w    = tid >> 5;
    const int lane = tid & 31;
    const int g    = lane >> 2;
    const int t    = lane & 3;
    const int qt   = (int)gridDim.x - 1 - (int)blockIdx.x;  // heavy CTAs first
    const int h    = blockIdx.y;
    const int b    = blockIdx.z;
    const int q_base = qt * 128;
    const int mb     = w * 16;

    const float* Qg = g_qkv + ((size_t)((0 * BB + b) * NH + h) * TT) * HD;
    const float* Kg = g_qkv + ((size_t)((1 * BB + b) * NH + h) * TT) * HD;
    const float* Vg = g_qkv + ((size_t)((2 * BB + b) * NH + h) * TT) * HD;

    int frow[4], fc4[4];
#pragma unroll
    for (int j = 0; j < 4; j++) {
        const int v = tid + 256 * j;
        frow[j] = v >> 4;
        fc4[j]  = (v & 15) * 4;
    }

    auto issue_kv = [&](int kt) {
        const int s = kt & 1;
        const uint32_t kb = smb + (uint32_t)(s * FK_TILE) * 4u;
        const uint32_t vb = vmb + (uint32_t)(s * FV_TILE) * 4u;
        const float* Kt = Kg + (size_t)(kt * 64) * HD;
        const float* Vt = Vg + (size_t)(kt * 64) * HD;
#pragma unroll
        for (int j = 0; j < 4; j++) {
            const size_t go = (size_t)frow[j] * HD + fc4[j];
            cpa16(kb + (uint32_t)(frow[j] * 68 + fc4[j]) * 4u, Kt + go);
            cpa16(vb + (uint32_t)(frow[j] * 72 + fc4[j]) * 4u, Vt + go);
        }
    };

    issue_kv(0); CP_COMMIT();

    // stage Q tile (data already tf32; *0.125 exact -> stays tf32)
    for (int i = tid; i < 2048; i += 256) {
        const int row = i >> 4, c4 = (i & 15) * 4;
        float4 v = *(const float4*)(Qg + (size_t)(q_base + row) * HD + c4);
        v.x *= 0.125f; v.y *= 0.125f; v.z *= 0.125f; v.w *= 0.125f;
        *(float4*)&Ps[row * 68 + c4] = v;
    }
    __syncthreads();

    uint32_t qa[8][4];
#pragma unroll
    for (int ks = 0; ks < 8; ks++) {
        const int kb = ks * 8;
        qa[ks][0] = __float_as_uint(Ps[(mb + g) * 68 + kb + t]);
        qa[ks][1] = __float_as_uint(Ps[(mb + g + 8) * 68 + kb + t]);
        qa[ks][2] = __float_as_uint(Ps[(mb + g) * 68 + kb + t + 4]);
        qa[ks][3] = __float_as_uint(Ps[(mb + g + 8) * 68 + kb + t + 4]);
    }

    float oacc[8][4];
#pragma unroll
    for (int nt = 0; nt < 8; nt++)
#pragma unroll
        for (int r = 0; r < 4; r++) oacc[nt][r] = 0.f;
    float m0 = -1e30f, m1 = -1e30f, l0 = 0.f, l1 = 0.f;
    const int r0 = q_base + mb + g, r1 = r0 + 8;

    const int nkt = 2 * qt + 2;
    for (int kt = 0; kt < nkt; kt++) {
        const int st = kt & 1;
        float* Ks = sm + st * FK_TILE;
        float* Vs = Vb + st * FV_TILE;

        CP_WAIT0();
        __syncthreads();   // tile kt visible; all warps done with stage st^1

        if (kt + 1 < nkt) issue_kv(kt + 1);
        CP_COMMIT();

        // S = Q @ K^T   (16x64 per warp)
        float sacc[8][4];
#pragma unroll
        for (int nt = 0; nt < 8; nt++)
#pragma unroll
            for (int r = 0; r < 4; r++) sacc[nt][r] = 0.f;
#pragma unroll
        for (int ks = 0; ks < 8; ks++) {
            const int kb = ks * 8;
            uint32_t bf[8][2];
#pragma unroll
            for (int nt = 0; nt < 8; nt++) {
                bf[nt][0] = __float_as_uint(Ks[(nt * 8 + g) * 68 + kb + t]);
                bf[nt][1] = __float_as_uint(Ks[(nt * 8 + g) * 68 + kb + t + 4]);
            }
#pragma unroll
            for (int nt = 0; nt < 8; nt++)
                mma_tf32(sacc[nt][0], sacc[nt][1], sacc[nt][2], sacc[nt][3],
                         qa[ks][0], qa[ks][1], qa[ks][2], qa[ks][3],
                         bf[nt][0], bf[nt][1]);
        }

        if (kt >= 2 * qt) {
            const int sb = kt * 64;
#pragma unroll
            for (int nt = 0; nt < 8; nt++) {
                const int c0 = sb + nt * 8 + 2 * t, c1 = c0 + 1;
                if (c0 > r0) sacc[nt][0] = -1e30f;
                if (c1 > r0) sacc[nt][1] = -1e30f;
                if (c0 > r1) sacc[nt][2] = -1e30f;
                if (c1 > r1) sacc[nt][3] = -1e30f;
            }
        }

        float mx0 = -1e30f, mx1 = -1e30f;
#pragma unroll
        for (int nt = 0; nt < 8; nt++) {
            mx0 = fmaxf(mx0, fmaxf(sacc[nt][0], sacc[nt][1]));
            mx1 = fmaxf(mx1, fmaxf(sacc[nt][2], sacc[nt][3]));
        }
        mx0 = fmaxf(mx0, __shfl_xor_sync(0xffffffffu, mx0, 1));
        mx0 = fmaxf(mx0, __shfl_xor_sync(0xffffffffu, mx0, 2));
        mx1 = fmaxf(mx1, __shfl_xor_sync(0xffffffffu, mx1, 1));
        mx1 = fmaxf(mx1, __shfl_xor_sync(0xffffffffu, mx1, 2));

        const float mn0 = fmaxf(m0, mx0), mn1 = fmaxf(m1, mx1);
        const float f0 = __expf(m0 - mn0), f1 = __expf(m1 - mn1);
        float ls0 = 0.f, ls1 = 0.f;
#pragma unroll
        for (int nt = 0; nt < 8; nt++) {
            const float p00 = __expf(sacc[nt][0] - mn0);
            const float p01 = __expf(sacc[nt][1] - mn0);
            const float p10 = __expf(sacc[nt][2] - mn1);
            const float p11 = __expf(sacc[nt][3] - mn1);
            ls0 += p00 + p01;
            ls1 += p10 + p11;
            float2 s0 = { to_tf32(p00), to_tf32(p01) };
            float2 s1 = { to_tf32(p10), to_tf32(p11) };
            *(float2*)&Ps[(mb + g) * 68 + nt * 8 + 2 * t]     = s0;
            *(float2*)&Ps[(mb + g + 8) * 68 + nt * 8 + 2 * t] = s1;
        }
        ls0 += __shfl_xor_sync(0xffffffffu, ls0, 1);
        ls0 += __shfl_xor_sync(0xffffffffu, ls0, 2);
        ls1 += __shfl_xor_sync(0xffffffffu, ls1, 1);
        ls1 += __shfl_xor_sync(0xffffffffu, ls1, 2);
        l0 = l0 * f0 + ls0;
        l1 = l1 * f1 + ls1;
        m0 = mn0; m1 = mn1;
#pragma unroll
        for (int nt = 0; nt < 8; nt++) {
            oacc[nt][0] *= f0; oacc[nt][1] *= f0;
            oacc[nt][2] *= f1; oacc[nt][3] *= f1;
        }
        __syncwarp();   // P rows are private to this warp

        // O += P @ V
#pragma unroll
        for (int ks = 0; ks < 8; ks++) {
            const int kb = ks * 8;
            uint32_t pa[4];
            pa[0] = __float_as_uint(Ps[(mb + g) * 68 + kb + t]);
            pa[1] = __float_as_uint(Ps[(mb + g + 8) * 68 + kb + t]);
            pa[2] = __float_as_uint(Ps[(mb + g) * 68 + kb + t + 4]);
            pa[3] = __float_as_uint(Ps[(mb + g + 8) * 68 + kb + t + 4]);
            uint32_t bf[8][2];
#pragma unroll
            for (int nt = 0; nt < 8; nt++) {
                bf[nt][0] = __float_as_uint(Vs[(kb + t) * 72 + nt * 8 + g]);
                bf[nt][1] = __float_as_uint(Vs[(kb + t + 4) * 72 + nt * 8 + g]);
            }
#pragma unroll
            for (int nt = 0; nt < 8; nt++)
                mma_tf32(oacc[nt][0], oacc[nt][1], oacc[nt][2], oacc[nt][3],
                         pa[0], pa[1], pa[2], pa[3], bf[nt][0], bf[nt][1]);
        }
    }

    // epilogue: tf32-round (proj GEMM rounds anyway -> identical numerics)
    const float i0 = 1.0f / l0, i1 = 1.0f / l1;
    float* O0 = g_att + ((size_t)(b * TT + r0) * NH + h) * HD;
    float* O1 = g_att + ((size_t)(b * TT + r1) * NH + h) * HD;
#pragma unroll
    for (int nt = 0; nt < 8; nt++) {
        const int d = nt * 8 + 2 * t;
        float2 o0 = { to_tf32(oacc[nt][0] * i0), to_tf32(oacc[nt][1] * i0) };
        float2 o1 = { to_tf32(oacc[nt][2] * i1), to_tf32(oacc[nt][3] * i1) };
        *(float2*)(O0 + d) = o0;
        *(float2*)(O1 + d) = o1;
    }
}

// ---------------------------------------------------------------------------
// kernel_launch
// ---------------------------------------------------------------------------
extern "C" void kernel_launch(void* const* d_in, const int* in_sizes, int n_in,
                              void* d_out, int out_size)
{
    const float* x      = (const float*)d_in[0];
    const float* w_qkv  = (const float*)d_in[1];
    const float* b_qkv  = (const float*)d_in[2];
    const float* w_proj = (const float*)d_in[3];
    const float* b_proj = (const float*)d_in[4];
    float* out = (float*)d_out;

    const int M = BB * TT;  // 4096

    cudaFuncSetAttribute(mma_gemm<0>, cudaFuncAttributeMaxDynamicSharedMemorySize, GSMEM_BYTES);
    cudaFuncSetAttribute(mma_gemm<1>, cudaFuncAttributeMaxDynamicSharedMemorySize, GSMEM_BYTES);
    cudaFuncSetAttribute(flash_mma, cudaFuncAttributeMaxDynamicSharedMemorySize, FLASH_SMEM);

    float* d_xr  = nullptr; cudaGetSymbolAddress((void**)&d_xr,  g_xr);
    float* d_wqr = nullptr; cudaGetSymbolAddress((void**)&d_wqr, g_wqr);
    float* d_wpr = nullptr; cudaGetSymbolAddress((void**)&d_wpr, g_wpr);

    // 0) prepass: tf32-round inputs (numerically identical to rounding at use)
    round_k<<<512, 256>>>(x,      d_xr,  BB * TT * DM / 4);
    round_k<<<512, 256>>>(w_qkv,  d_wqr, DM * 3 * DM / 4);
    round_k<<<512, 256>>>(w_proj, d_wpr, DM * DM / 4);

    // 1) QKV projection (tf32 mma.sync, BK=32, 3-stage cp.async) -> g_qkv
    mma_gemm<0><<<dim3(3 * DM / 128, M / 128), 256, GSMEM_BYTES>>>(b_qkv, nullptr, M, 3 * DM, DM);

    // 2) causal flash attention (tf32 mma.sync, cp.async K/V) -> g_att
    flash_mma<<<dim3(TT / 128, NH, BB), 256, FLASH_SMEM>>>();

    // 3) output projection -> out
    mma_gemm<1><<<dim3(DM / 128, M / 128), 256, GSMEM_BYTES>>>(b_proj, out, M, DM, DM);
}

// round 10
// speedup vs baseline: 2.0386x; 1.0147x over previous
#include <cuda_runtime.h>
#include <cstdint>

// Problem constants
#define DM   1024
#define NH   16
#define HD   64
#define BB   2
#define TT   2048

// Scratch (device globals: allocation-free rule)
__device__ float g_qkv[3 * BB * NH * TT * HD];   // [which][b][h][t][d], tf32-rounded
__device__ float g_att[BB * TT * DM];            // [b][t][h][d], tf32-rounded
__device__ float g_xr[BB * TT * DM];             // x, tf32-rounded
__device__ float g_wqr[DM * 3 * DM];             // w_qkv, tf32-rounded
__device__ float g_wpr[DM * DM];                 // w_proj, tf32-rounded

// ---------------------------------------------------------------------------
// tf32 helpers (portable PTX: works on plain sm_103 target)
// ---------------------------------------------------------------------------
__device__ __forceinline__ float to_tf32(float x) {
    uint32_t u;
    asm("cvt.rna.tf32.f32 %0, %1;" : "=r"(u) : "f"(x));
    return __uint_as_float(u);
}
__device__ __forceinline__ float ex2(float x) {
    float r;
    asm("ex2.approx.f32 %0, %1;" : "=f"(r) : "f"(x));
    return r;
}

__device__ __forceinline__ void mma_tf32(float& c0, float& c1, float& c2, float& c3,
                                         uint32_t a0, uint32_t a1, uint32_t a2, uint32_t a3,
                                         uint32_t b0, uint32_t b1) {
    asm volatile(
        "mma.sync.aligned.m16n8k8.row.col.f32.tf32.tf32.f32 "
        "{%0,%1,%2,%3}, {%4,%5,%6,%7}, {%8,%9}, {%0,%1,%2,%3};"
        : "+f"(c0), "+f"(c1), "+f"(c2), "+f"(c3)
        : "r"(a0), "r"(a1), "r"(a2), "r"(a3), "r"(b0), "r"(b1));
}

__device__ __forceinline__ uint32_t smem_u32(const void* p) {
    uint32_t a;
    asm("{ .reg .u64 t; cvta.to.shared.u64 t, %1; cvt.u32.u64 %0, t; }"
        : "=r"(a) : "l"(p));
    return a;
}
__device__ __forceinline__ void cpa16(uint32_t saddr, const void* g) {
    asm volatile("cp.async.cg.shared.global [%0], [%1], 16;"
                 :: "r"(saddr), "l"(g) : "memory");
}
#define CP_COMMIT() asm volatile("cp.async.commit_group;" ::: "memory")
#define CP_WAIT1()  asm volatile("cp.async.wait_group 1;" ::: "memory")
#define CP_WAIT0()  asm volatile("cp.async.wait_group 0;" ::: "memory")

// ---------------------------------------------------------------------------
// Merged prepass: tf32-round x, w_qkv, w_proj in one launch (float4 strides)
// ---------------------------------------------------------------------------
#define N4_X  (BB * TT * DM / 4)
#define N4_WQ (DM * 3 * DM / 4)
#define N4_WP (DM * DM / 4)

__global__ __launch_bounds__(256) void round_all(const float* __restrict__ x,
                                                 const float* __restrict__ wq,
                                                 const float* __restrict__ wp)
{
    const int total = N4_X + N4_WQ + N4_WP;
    const int stride = gridDim.x * blockDim.x;
    for (int i = blockIdx.x * blockDim.x + threadIdx.x; i < total; i += stride) {
        const float* src;
        float* dst;
        int j = i;
        if (j < N4_X) { src = x; dst = (float*)g_xr; }
        else if ((j -= N4_X) < N4_WQ) { src = wq; dst = (float*)g_wqr; }
        else { j -= N4_WQ; src = wp; dst = (float*)g_wpr; }
        float4 v = *(const float4*)(src + (size_t)j * 4);
        v.x = to_tf32(v.x); v.y = to_tf32(v.y);
        v.z = to_tf32(v.z); v.w = to_tf32(v.w);
        *(float4*)(dst + (size_t)j * 4) = v;
    }
}

// ---------------------------------------------------------------------------
// tf32 tensor-core GEMM, BK=32, 3-stage cp.async pipeline, pre-rounded
// inputs (unchanged from R9).
// ---------------------------------------------------------------------------
#define AS_STRIDE (128 * 36)
#define BS_STRIDE (32 * 136)
#define GSMEM_BYTES ((3 * AS_STRIDE + 3 * BS_STRIDE) * 4)

template <int MODE>
__global__ __launch_bounds__(256) void mma_gemm(const float* __restrict__ bias,
                                                float* __restrict__ C,
                                                int M, int N, int K)
{
    extern __shared__ float dsm[];
    float* AsF = dsm;
    float* BsF = dsm + 3 * AS_STRIDE;
    const uint32_t abase = smem_u32(AsF);
    const uint32_t bbase = smem_u32(BsF);

    const int tid  = threadIdx.x;
    const int bm   = blockIdx.y * 128;
    const int bn   = blockIdx.x * 128;
    const int w    = tid >> 5;
    const int lane = tid & 31;
    const int g    = lane >> 2;
    const int t    = lane & 3;
    const int m0   = (w & 3) * 32;
    const int n0   = (w >> 2) * 64;

    const float* Aeff = (MODE == 0) ? (const float*)g_xr : (const float*)g_att;
    const float* Bw   = (MODE == 0) ? (const float*)g_wqr : (const float*)g_wpr;

    float acc[2][8][4];
#pragma unroll
    for (int mt = 0; mt < 2; mt++)
#pragma unroll
        for (int nt = 0; nt < 8; nt++)
#pragma unroll
            for (int r = 0; r < 4; r++) acc[mt][nt][r] = 0.f;

    int arow[4], ac4[4], brow[4], bc4[4];
#pragma unroll
    for (int j = 0; j < 4; j++) {
        const int f = tid + 256 * j;
        arow[j] = f >> 3;  ac4[j] = (f & 7) * 4;
        brow[j] = f >> 5;  bc4[j] = (f & 31) * 4;
    }

    const int NC = K >> 5;

    auto issue = [&](int c) {
        const int s = c % 3;
        const uint32_t as = abase + (uint32_t)(s * AS_STRIDE) * 4u;
        const uint32_t bs = bbase + (uint32_t)(s * BS_STRIDE) * 4u;
        const int k0 = c << 5;
#pragma unroll
        for (int j = 0; j < 4; j++) {
            cpa16(as + (uint32_t)(arow[j] * 36 + ac4[j]) * 4u,
                  Aeff + (size_t)(bm + arow[j]) * K + k0 + ac4[j]);
            cpa16(bs + (uint32_t)(brow[j] * 136 + bc4[j]) * 4u,
                  Bw + (size_t)(k0 + brow[j]) * N + bn + bc4[j]);
        }
    };

    issue(0); CP_COMMIT();
    issue(1); CP_COMMIT();

    for (int c = 0; c < NC; c++) {
        const int st = c % 3;
        CP_WAIT1();
        __syncthreads();

        if (c + 2 < NC) issue(c + 2);
        CP_COMMIT();

        const float* As = AsF + st * AS_STRIDE;
        const float* Bs = BsF + st * BS_STRIDE;
#pragma unroll
        for (int ks = 0; ks < 4; ks++) {
            const int kb = ks * 8;
            uint32_t af[2][4], bf[8][2];
#pragma unroll
            for (int mt = 0; mt < 2; mt++) {
                const int m = m0 + mt * 16 + g;
                af[mt][0] = __float_as_uint(As[m * 36 + kb + t]);
                af[mt][1] = __float_as_uint(As[(m + 8) * 36 + kb + t]);
                af[mt][2] = __float_as_uint(As[m * 36 + kb + t + 4]);
                af[mt][3] = __float_as_uint(As[(m + 8) * 36 + kb + t + 4]);
            }
#pragma unroll
            for (int nt = 0; nt < 8; nt++) {
                const int n = n0 + nt * 8 + g;
                bf[nt][0] = __float_as_uint(Bs[(kb + t) * 136 + n]);
                bf[nt][1] = __float_as_uint(Bs[(kb + t + 4) * 136 + n]);
            }
#pragma unroll
            for (int mt = 0; mt < 2; mt++)
#pragma unroll
                for (int nt = 0; nt < 8; nt++)
                    mma_tf32(acc[mt][nt][0], acc[mt][nt][1],
                             acc[mt][nt][2], acc[mt][nt][3],
                             af[mt][0], af[mt][1], af[mt][2], af[mt][3],
                             bf[nt][0], bf[nt][1]);
        }
    }

    const int ng = bn + n0;
    if (MODE == 0) {
        const int which = ng >> 10;
        const int rem   = ng & 1023;
        const int h     = rem >> 6;
#pragma unroll
        for (int mt = 0; mt < 2; mt++) {
            const int row0 = bm + m0 + mt * 16 + g;
            const int row1 = row0 + 8;
            const int b0i = row0 >> 11, t0i = row0 & 2047;
            const int b1i = row1 >> 11, t1i = row1 & 2047;
            float* base0 = g_qkv + ((size_t)((which * BB + b0i) * NH + h) * TT + t0i) * HD;
            float* base1 = g_qkv + ((size_t)((which * BB + b1i) * NH + h) * TT + t1i) * HD;
#pragma unroll
            for (int nt = 0; nt < 8; nt++) {
                const int d = nt * 8 + 2 * t;
                const float bx = bias[ng + d], by = bias[ng + d + 1];
                float2 o0 = { to_tf32(acc[mt][nt][0] + bx), to_tf32(acc[mt][nt][1] + by) };
                float2 o1 = { to_tf32(acc[mt][nt][2] + bx), to_tf32(acc[mt][nt][3] + by) };
                *(float2*)(base0 + d) = o0;
                *(float2*)(base1 + d) = o1;
            }
        }
    } else {
#pragma unroll
        for (int mt = 0; mt < 2; mt++) {
            const int row0 = bm + m0 + mt * 16 + g;
            const int row1 = row0 + 8;
#pragma unroll
            for (int nt = 0; nt < 8; nt++) {
                const int n = ng + nt * 8 + 2 * t;
                const float bx = bias[n], by = bias[n + 1];
                float2 o0 = { acc[mt][nt][0] + bx, acc[mt][nt][1] + by };
                float2 o1 = { acc[mt][nt][2] + bx, acc[mt][nt][3] + by };
                *(float2*)(C + (size_t)row0 * N + n) = o0;
                *(float2*)(C + (size_t)row1 * N + n) = o1;
            }
        }
    }
}

// ---------------------------------------------------------------------------
// Flash attention, tf32 mma.sync, pre-rounded inputs, 2-stage cp.async K/V.
// This round: (a) exp2-domain softmax (log2e folded into Q prescale),
// (b) warps skip fully-masked diagonal tiles (bit-exact skip).
// ---------------------------------------------------------------------------
#define FK_TILE  (64 * 68)
#define FV_TILE  (64 * 72)
#define FLASH_SMEM ((2 * FK_TILE + 2 * FV_TILE + 128 * 68) * 4)

__global__ __launch_bounds__(256, 2) void flash_mma()
{
    extern __shared__ float sm[];
    float* Vb = sm + 2 * FK_TILE;
    float* Ps = sm + 2 * FK_TILE + 2 * FV_TILE;    // [128][68]: Q staging, then P
    const uint32_t smb = smem_u32(sm);
    const uint32_t vmb = smem_u32(Vb);

    const int tid  = threadIdx.x;
    const int w    = tid >> 5;
    const int lane = tid & 31;
    const int g    = lane >> 2;
    const int t    = lane & 3;
    const int qt   = (int)gridDim.x - 1 - (int)blockIdx.x;  // heavy CTAs first
    const int h    = blockIdx.y;
    const int b    = blockIdx.z;
    const int q_base = qt * 128;
    const int mb     = w * 16;

    const float* Qg = g_qkv + ((size_t)((0 * BB + b) * NH + h) * TT) * HD;
    const float* Kg = g_qkv + ((size_t)((1 * BB + b) * NH + h) * TT) * HD;
    const float* Vg = g_qkv + ((size_t)((2 * BB + b) * NH + h) * TT) * HD;

    int frow[4], fc4[4];
#pragma unroll
    for (int j = 0; j < 4; j++) {
        const int v = tid + 256 * j;
        frow[j] = v >> 4;
        fc4[j]  = (v & 15) * 4;
    }

    auto issue_kv = [&](int kt) {
        const int s = kt & 1;
        const uint32_t kb = smb + (uint32_t)(s * FK_TILE) * 4u;
        const uint32_t vb = vmb + (uint32_t)(s * FV_TILE) * 4u;
        const float* Kt = Kg + (size_t)(kt * 64) * HD;
        const float* Vt = Vg + (size_t)(kt * 64) * HD;
#pragma unroll
        for (int j = 0; j < 4; j++) {
            const size_t go = (size_t)frow[j] * HD + fc4[j];
            cpa16(kb + (uint32_t)(frow[j] * 68 + fc4[j]) * 4u, Kt + go);
            cpa16(vb + (uint32_t)(frow[j] * 72 + fc4[j]) * 4u, Vt + go);
        }
    };

    issue_kv(0); CP_COMMIT();

    // stage Q tile, prescaled by (1/sqrt(64)) * log2(e) and tf32-rounded.
    // Softmax then runs in the exp2 domain (bare MUFU.EX2, no FMUL).
    const float QS = 0.18033688011112042f;  // 0.125 * log2(e)
    for (int i = tid; i < 2048; i += 256) {
        const int row = i >> 4, c4 = (i & 15) * 4;
        float4 v = *(const float4*)(Qg + (size_t)(q_base + row) * HD + c4);
        v.x = to_tf32(v.x * QS); v.y = to_tf32(v.y * QS);
        v.z = to_tf32(v.z * QS); v.w = to_tf32(v.w * QS);
        *(float4*)&Ps[row * 68 + c4] = v;
    }
    __syncthreads();

    uint32_t qa[8][4];
#pragma unroll
    for (int ks = 0; ks < 8; ks++) {
        const int kb = ks * 8;
        qa[ks][0] = __float_as_uint(Ps[(mb + g) * 68 + kb + t]);
        qa[ks][1] = __float_as_uint(Ps[(mb + g + 8) * 68 + kb + t]);
        qa[ks][2] = __float_as_uint(Ps[(mb + g) * 68 + kb + t + 4]);
        qa[ks][3] = __float_as_uint(Ps[(mb + g + 8) * 68 + kb + t + 4]);
    }

    float oacc[8][4];
#pragma unroll
    for (int nt = 0; nt < 8; nt++)
#pragma unroll
        for (int r = 0; r < 4; r++) oacc[nt][r] = 0.f;
    float m0 = -1e30f, m1 = -1e30f, l0 = 0.f, l1 = 0.f;
    const int r0 = q_base + mb + g, r1 = r0 + 8;

    const int nkt = 2 * qt + 2;
    for (int kt = 0; kt < nkt; kt++) {
        const int st = kt & 1;
        float* Ks = sm + st * FK_TILE;
        float* Vs = Vb + st * FV_TILE;

        CP_WAIT0();
        __syncthreads();   // tile kt visible; all warps done with stage st^1

        if (kt + 1 < nkt) issue_kv(kt + 1);
        CP_COMMIT();

        // warp-level causal skip: if every column of this key tile is above
        // this warp's rows, the tile contributes exactly zero -> skip all
        // compute (bit-identical; barriers already passed).
        if (kt * 64 > q_base + mb + 15) continue;

        // S = Q @ K^T   (16x64 per warp)
        float sacc[8][4];
#pragma unroll
        for (int nt = 0; nt < 8; nt++)
#pragma unroll
            for (int r = 0; r < 4; r++) sacc[nt][r] = 0.f;
#pragma unroll
        for (int ks = 0; ks < 8; ks++) {
            const int kb = ks * 8;
            uint32_t bf[8][2];
#pragma unroll
            for (int nt = 0; nt < 8; nt++) {
                bf[nt][0] = __float_as_uint(Ks[(nt * 8 + g) * 68 + kb + t]);
                bf[nt][1] = __float_as_uint(Ks[(nt * 8 + g) * 68 + kb + t + 4]);
            }
#pragma unroll
            for (int nt = 0; nt < 8; nt++)
                mma_tf32(sacc[nt][0], sacc[nt][1], sacc[nt][2], sacc[nt][3],
                         qa[ks][0], qa[ks][1], qa[ks][2], qa[ks][3],
                         bf[nt][0], bf[nt][1]);
        }

        if (kt >= 2 * qt) {
            const int sb = kt * 64;
#pragma unroll
            for (int nt = 0; nt < 8; nt++) {
                const int c0 = sb + nt * 8 + 2 * t, c1 = c0 + 1;
                if (c0 > r0) sacc[nt][0] = -1e30f;
                if (c1 > r0) sacc[nt][1] = -1e30f;
                if (c0 > r1) sacc[nt][2] = -1e30f;
                if (c1 > r1) sacc[nt][3] = -1e30f;
            }
        }

        float mx0 = -1e30f, mx1 = -1e30f;
#pragma unroll
        for (int nt = 0; nt < 8; nt++) {
            mx0 = fmaxf(mx0, fmaxf(sacc[nt][0], sacc[nt][1]));
            mx1 = fmaxf(mx1, fmaxf(sacc[nt][2], sacc[nt][3]));
        }
        mx0 = fmaxf(mx0, __shfl_xor_sync(0xffffffffu, mx0, 1));
        mx0 = fmaxf(mx0, __shfl_xor_sync(0xffffffffu, mx0, 2));
        mx1 = fmaxf(mx1, __shfl_xor_sync(0xffffffffu, mx1, 1));
        mx1 = fmaxf(mx1, __shfl_xor_sync(0xffffffffu, mx1, 2));

        const float mn0 = fmaxf(m0, mx0), mn1 = fmaxf(m1, mx1);
        const float f0 = ex2(m0 - mn0), f1 = ex2(m1 - mn1);
        float ls0 = 0.f, ls1 = 0.f;
#pragma unroll
        for (int nt = 0; nt < 8; nt++) {
            const float p00 = ex2(sacc[nt][0] - mn0);
            const float p01 = ex2(sacc[nt][1] - mn0);
            const float p10 = ex2(sacc[nt][2] - mn1);
            const float p11 = ex2(sacc[nt][3] - mn1);
            ls0 += p00 + p01;
            ls1 += p10 + p11;
            float2 s0 = { to_tf32(p00), to_tf32(p01) };
            float2 s1 = { to_tf32(p10), to_tf32(p11) };
            *(float2*)&Ps[(mb + g) * 68 + nt * 8 + 2 * t]     = s0;
            *(float2*)&Ps[(mb + g + 8) * 68 + nt * 8 + 2 * t] = s1;
        }
        ls0 += __shfl_xor_sync(0xffffffffu, ls0, 1);
        ls0 += __shfl_xor_sync(0xffffffffu, ls0, 2);
        ls1 += __shfl_xor_sync(0xffffffffu, ls1, 1);
        ls1 += __shfl_xor_sync(0xffffffffu, ls1, 2);
        l0 = l0 * f0 + ls0;
        l1 = l1 * f1 + ls1;
        m0 = mn0; m1 = mn1;
#pragma unroll
        for (int nt = 0; nt < 8; nt++) {
            oacc[nt][0] *= f0; oacc[nt][1] *= f0;
            oacc[nt][2] *= f1; oacc[nt][3] *= f1;
        }
        __syncwarp();   // P rows are private to this warp

        // O += P @ V
#pragma unroll
        for (int ks = 0; ks < 8; ks++) {
            const int kb = ks * 8;
            uint32_t pa[4];
            pa[0] = __float_as_uint(Ps[(mb + g) * 68 + kb + t]);
            pa[1] = __float_as_uint(Ps[(mb + g + 8) * 68 + kb + t]);
            pa[2] = __float_as_uint(Ps[(mb + g) * 68 + kb + t + 4]);
            pa[3] = __float_as_uint(Ps[(mb + g + 8) * 68 + kb + t + 4]);
            uint32_t bf[8][2];
#pragma unroll
            for (int nt = 0; nt < 8; nt++) {
                bf[nt][0] = __float_as_uint(Vs[(kb + t) * 72 + nt * 8 + g]);
                bf[nt][1] = __float_as_uint(Vs[(kb + t + 4) * 72 + nt * 8 + g]);
            }
#pragma unroll
            for (int nt = 0; nt < 8; nt++)
                mma_tf32(oacc[nt][0], oacc[nt][1], oacc[nt][2], oacc[nt][3],
                         pa[0], pa[1], pa[2], pa[3], bf[nt][0], bf[nt][1]);
        }
    }

    // epilogue: tf32-round (proj GEMM rounds anyway -> identical numerics)
    const float i0 = 1.0f / l0, i1 = 1.0f / l1;
    float* O0 = g_att + ((size_t)(b * TT + r0) * NH + h) * HD;
    float* O1 = g_att + ((size_t)(b * TT + r1) * NH + h) * HD;
#pragma unroll
    for (int nt = 0; nt < 8; nt++) {
        const int d = nt * 8 + 2 * t;
        float2 o0 = { to_tf32(oacc[nt][0] * i0), to_tf32(oacc[nt][1] * i0) };
        float2 o1 = { to_tf32(oacc[nt][2] * i1), to_tf32(oacc[nt][3] * i1) };
        *(float2*)(O0 + d) = o0;
        *(float2*)(O1 + d) = o1;
    }
}

// ---------------------------------------------------------------------------
// kernel_launch
// ---------------------------------------------------------------------------
extern "C" void kernel_launch(void* const* d_in, const int* in_sizes, int n_in,
                              void* d_out, int out_size)
{
    const float* x      = (const float*)d_in[0];
    const float* w_qkv  = (const float*)d_in[1];
    const float* b_qkv  = (const float*)d_in[2];
    const float* w_proj = (const float*)d_in[3];
    const float* b_proj = (const float*)d_in[4];
    float* out = (float*)d_out;

    const int M = BB * TT;  // 4096

    cudaFuncSetAttribute(mma_gemm<0>, cudaFuncAttributeMaxDynamicSharedMemorySize, GSMEM_BYTES);
    cudaFuncSetAttribute(mma_gemm<1>, cudaFuncAttributeMaxDynamicSharedMemorySize, GSMEM_BYTES);
    cudaFuncSetAttribute(flash_mma, cudaFuncAttributeMaxDynamicSharedMemorySize, FLASH_SMEM);

    // 0) merged prepass: tf32-round x, w_qkv, w_proj (one launch)
    round_all<<<1024, 256>>>(x, w_qkv, w_proj);

    // 1) QKV projection (tf32 mma.sync, BK=32, 3-stage cp.async) -> g_qkv
    mma_gemm<0><<<dim3(3 * DM / 128, M / 128), 256, GSMEM_BYTES>>>(b_qkv, nullptr, M, 3 * DM, DM);

    // 2) causal flash attention (tf32 mma.sync, cp.async K/V, exp2 softmax,
    //    warp-level causal skip) -> g_att
    flash_mma<<<dim3(TT / 128, NH, BB), 256, FLASH_SMEM>>>();

    // 3) output projection -> out
    mma_gemm<1><<<dim3(DM / 128, M / 128), 256, GSMEM_BYTES>>>(b_proj, out, M, DM, DM);
}